// round 6
// baseline (speedup 1.0000x reference)
#include <cuda_runtime.h>
#include <cuda_bf16.h>
#include <cstdint>

typedef __nv_bfloat16 bf16;

static const int NU = 50000;
static const int NV = 50000;
static const int NE = 500000;
static const int NALL = 100000;          // concatenated dst-node space
#define NEG_SLOPE 0.2f
#define EPS_F 1e-16f

// fused-launch geometry: 782 gemm blocks : 6250 agg blocks, interleave 1:9
#define FUSED_T 7032
#define GSMEM 81920

// ---------------------------------------------------------------------------
// Static device scratch
// ---------------------------------------------------------------------------
__device__ __align__(128) float g_hs0[50048 * 256];
__device__ __align__(128) float g_hs1[50048 * 256];
__device__ __align__(128) bf16 g_xu_hi[50048 * 256], g_xu_lo[50048 * 256];
__device__ __align__(128) bf16 g_xv_hi[50048 * 256], g_xv_lo[50048 * 256];
__device__ __align__(128) bf16 g_nv0_hi[50048 * 256], g_nv0_lo[50048 * 256];
__device__ __align__(128) bf16 g_nu0_hi[50048 * 256], g_nu0_lo[50048 * 256];
__device__ __align__(128) bf16 g_nu1_hi[50048 * 256], g_nu1_lo[50048 * 256];
__device__ __align__(128) float g_es0[50048 * 4], g_es1[50048 * 4], g_es2[50048 * 4];
__device__ __align__(128) float g_ed0[50048 * 4], g_ed1[50048 * 4], g_ed2[50048 * 4];
__device__ __align__(128) float g_cmbT_u[8 * 256], g_cmbT_v[8 * 256];
__device__ __align__(128) float g_wsatt2T[4 * 256], g_vd2T[4 * 256];
__device__ __align__(128) bf16 g_wt_hi[3 * 256 * 256], g_wt_lo[3 * 256 * 256];
__device__ __align__(128) bf16 g_lt_hi[128 * 256], g_lt_lo[128 * 256];
__device__ __align__(128) int g_rowptr[100001];
__device__ __align__(128) int g_csrc[1000000];
__device__ __align__(128) int g_cnt[100001], g_bsums[128];

// ---------------------------------------------------------------------------
// helpers
// ---------------------------------------------------------------------------
__device__ __forceinline__ uint32_t smem_u32(const void* p) {
    uint32_t a;
    asm("{ .reg .u64 t; cvta.to.shared.u64 t, %1; cvt.u32.u64 %0, t; }"
        : "=r"(a) : "l"(p));
    return a;
}

__device__ __forceinline__ void cp16(uint32_t dst, const void* src) {
    asm volatile("cp.async.cg.shared.global [%0], [%1], 16;"
                 :: "r"(dst), "l"(src));
}

__device__ __forceinline__ void ldsm4(uint32_t& r0, uint32_t& r1, uint32_t& r2,
                                      uint32_t& r3, uint32_t addr) {
    asm volatile("ldmatrix.sync.aligned.m8n8.x4.shared.b16 {%0,%1,%2,%3}, [%4];"
                 : "=r"(r0), "=r"(r1), "=r"(r2), "=r"(r3) : "r"(addr));
}

__device__ __forceinline__ void mma_bf16(float* c, const uint32_t* a,
                                         const uint32_t* b) {
    asm volatile(
        "mma.sync.aligned.m16n8k16.row.col.f32.bf16.bf16.f32 "
        "{%0,%1,%2,%3}, {%4,%5,%6,%7}, {%8,%9}, {%0,%1,%2,%3};"
        : "+f"(c[0]), "+f"(c[1]), "+f"(c[2]), "+f"(c[3])
        : "r"(a[0]), "r"(a[1]), "r"(a[2]), "r"(a[3]), "r"(b[0]), "r"(b[1]));
}

// ---------------------------------------------------------------------------
// GEMM block body: C[128,NSTR tile] at (bm,bn) = (Ahi+Alo)@(Bhi+Blo)^T
// 2-stage cp.async, ONE __syncthreads per k-iter.
// ---------------------------------------------------------------------------
template<int NSTR, bool BIAS>
__device__ __forceinline__ void gemm_block(
    int bm, int bn,
    const bf16* __restrict__ Ahi, const bf16* __restrict__ Alo,
    const bf16* __restrict__ Bhi, const bf16* __restrict__ Blo,
    const float* __restrict__ bias, float* __restrict__ C, int M) {
    extern __shared__ __align__(128) char smg[];
    const uint32_t sb = smem_u32(smg);
    const int tid = threadIdx.x, lane = tid & 31, wid = tid >> 5;
    const int wm = wid >> 2, wn = wid & 3;

    const char* src[4] = {
        (const char*)(Ahi + (size_t)bm * 256), (const char*)(Alo + (size_t)bm * 256),
        (const char*)(Bhi + (size_t)bn * 256), (const char*)(Blo + (size_t)bn * 256)};

    uint32_t aBH[4], aBL[4], bBH[2], bBL[2];
    {
        int ar = wm * 64 + (lane & 15), ac = (lane >> 4) * 8;
        #pragma unroll
        for (int i = 0; i < 4; i++) {
            aBH[i] = sb + (uint32_t)(ar + i * 16) * 80 + ac * 2;
            aBL[i] = aBH[i] + 10240;
        }
        int br = wn * 32 + ((lane >> 4) << 3) + (lane & 7);
        int bc = ((lane >> 3) & 1) * 8;
        #pragma unroll
        for (int p = 0; p < 2; p++) {
            bBH[p] = sb + 20480 + (uint32_t)(br + p * 16) * 80 + bc * 2;
            bBL[p] = bBH[p] + 10240;
        }
    }

    float acc[4][4][4];
    #pragma unroll
    for (int i = 0; i < 4; i++)
        #pragma unroll
        for (int j = 0; j < 4; j++)
            #pragma unroll
            for (int q = 0; q < 4; q++) acc[i][j][q] = 0.f;

    auto load_stage = [&](int kc, int buf) {
        #pragma unroll
        for (int arr = 0; arr < 4; arr++) {
            const char* s = src[arr] + kc * 64;
            uint32_t d = sb + buf * 40960 + arr * 10240;
            #pragma unroll
            for (int t2 = 0; t2 < 2; t2++) {
                int cid = t2 * 256 + tid, row = cid >> 2, c = cid & 3;
                cp16(d + row * 80 + c * 16, s + (size_t)row * 512 + c * 16);
            }
        }
        asm volatile("cp.async.commit_group;");
    };

    load_stage(0, 0);
    for (int kc = 0; kc < 8; kc++) {
        int buf = kc & 1;
        asm volatile("cp.async.wait_group 0;");
        __syncthreads();
        if (kc < 7) load_stage(kc + 1, buf ^ 1);
        uint32_t bo = (uint32_t)buf * 40960;
        #pragma unroll
        for (int ks = 0; ks < 2; ks++) {
            uint32_t ah[4][4], al[4][4], bh[4][2], bl[4][2];
            #pragma unroll
            for (int i = 0; i < 4; i++) {
                ldsm4(ah[i][0], ah[i][1], ah[i][2], ah[i][3], aBH[i] + bo + ks * 32);
                ldsm4(al[i][0], al[i][1], al[i][2], al[i][3], aBL[i] + bo + ks * 32);
            }
            #pragma unroll
            for (int p = 0; p < 2; p++) {
                uint32_t r0, r1, r2, r3;
                ldsm4(r0, r1, r2, r3, bBH[p] + bo + ks * 32);
                bh[p * 2][0] = r0; bh[p * 2][1] = r1;
                bh[p * 2 + 1][0] = r2; bh[p * 2 + 1][1] = r3;
                ldsm4(r0, r1, r2, r3, bBL[p] + bo + ks * 32);
                bl[p * 2][0] = r0; bl[p * 2][1] = r1;
                bl[p * 2 + 1][0] = r2; bl[p * 2 + 1][1] = r3;
            }
            #pragma unroll
            for (int i = 0; i < 4; i++)
                #pragma unroll
                for (int j = 0; j < 4; j++) {
                    mma_bf16(acc[i][j], ah[i], bh[j]);
                    mma_bf16(acc[i][j], ah[i], bl[j]);
                    mma_bf16(acc[i][j], al[i], bh[j]);
                }
        }
    }

    #pragma unroll
    for (int i = 0; i < 4; i++) {
        int r0 = bm + wm * 64 + i * 16 + (lane >> 2);
        #pragma unroll
        for (int j = 0; j < 4; j++) {
            int cc = bn + wn * 32 + j * 8 + 2 * (lane & 3);
            float b0 = 0.f, b1 = 0.f;
            if (BIAS) { b0 = __ldg(&bias[cc]); b1 = __ldg(&bias[cc + 1]); }
            if (r0 < M)
                *(float2*)&C[(size_t)r0 * NSTR + cc] =
                    make_float2(acc[i][j][0] + b0, acc[i][j][1] + b1);
            if (r0 + 8 < M)
                *(float2*)&C[(size_t)(r0 + 8) * NSTR + cc] =
                    make_float2(acc[i][j][2] + b0, acc[i][j][3] + b1);
        }
    }
}

// ---------------------------------------------------------------------------
// Aggregation block body (warp/node), edge loop unrolled x2.
// ---------------------------------------------------------------------------
template<int AUX>
__device__ __forceinline__ void agg_block(
    int ablk, const float* __restrict__ hs, const float* __restrict__ es,
    const float* __restrict__ ed, const int* __restrict__ rowptr,
    const int* __restrict__ csrc, const float* __restrict__ bias,
    bf16* __restrict__ outhi, bf16* __restrict__ outlo,
    const float* __restrict__ auxT, float* __restrict__ auxout, int Nd) {
    __shared__ float saux[1024];
    if (AUX) {
        for (int i = threadIdx.x; i < 1024; i += 256) saux[i] = auxT[i];
        __syncthreads();
    }
    int warp = ablk * 8 + (threadIdx.x >> 5);
    int lane = threadIdx.x & 31;
    if (warp >= Nd) return;
    int h = lane >> 3;
    float edh = ed[warp * 4 + h];
    int beg = rowptr[warp], end = rowptr[warp + 1];
    float denom = 0.f;
    float acc[8] = {0.f, 0.f, 0.f, 0.f, 0.f, 0.f, 0.f, 0.f};
    int e = beg;
    for (; e + 2 <= end; e += 2) {
        int s0 = csrc[e], s1 = csrc[e + 1];
        float a0 = es[s0 * 4 + h] + edh;
        float a1 = es[s1 * 4 + h] + edh;
        a0 = (a0 > 0.f) ? a0 : a0 * NEG_SLOPE;
        a1 = (a1 > 0.f) ? a1 : a1 * NEG_SLOPE;
        float w0 = __expf(a0), w1 = __expf(a1);
        denom += w0 + w1;
        const float4* r0 = (const float4*)&hs[(size_t)s0 * 256 + lane * 8];
        const float4* r1 = (const float4*)&hs[(size_t)s1 * 256 + lane * 8];
        float4 p0 = r0[0], p1 = r0[1], q0 = r1[0], q1 = r1[1];
        acc[0] = fmaf(w0, p0.x, acc[0]); acc[1] = fmaf(w0, p0.y, acc[1]);
        acc[2] = fmaf(w0, p0.z, acc[2]); acc[3] = fmaf(w0, p0.w, acc[3]);
        acc[4] = fmaf(w0, p1.x, acc[4]); acc[5] = fmaf(w0, p1.y, acc[5]);
        acc[6] = fmaf(w0, p1.z, acc[6]); acc[7] = fmaf(w0, p1.w, acc[7]);
        acc[0] = fmaf(w1, q0.x, acc[0]); acc[1] = fmaf(w1, q0.y, acc[1]);
        acc[2] = fmaf(w1, q0.z, acc[2]); acc[3] = fmaf(w1, q0.w, acc[3]);
        acc[4] = fmaf(w1, q1.x, acc[4]); acc[5] = fmaf(w1, q1.y, acc[5]);
        acc[6] = fmaf(w1, q1.z, acc[6]); acc[7] = fmaf(w1, q1.w, acc[7]);
    }
    if (e < end) {
        int s = csrc[e];
        float a = es[s * 4 + h] + edh;
        a = (a > 0.f) ? a : a * NEG_SLOPE;
        float w = __expf(a);
        denom += w;
        const float4* r = (const float4*)&hs[(size_t)s * 256 + lane * 8];
        float4 v0 = r[0], v1 = r[1];
        acc[0] = fmaf(w, v0.x, acc[0]); acc[1] = fmaf(w, v0.y, acc[1]);
        acc[2] = fmaf(w, v0.z, acc[2]); acc[3] = fmaf(w, v0.w, acc[3]);
        acc[4] = fmaf(w, v1.x, acc[4]); acc[5] = fmaf(w, v1.y, acc[5]);
        acc[6] = fmaf(w, v1.z, acc[6]); acc[7] = fmaf(w, v1.w, acc[7]);
    }
    float inv = 1.f / (denom + EPS_F);
    const float4* bp = (const float4*)&bias[lane * 8];
    float4 b0 = bp[0], b1 = bp[1];
    float o[8];
    o[0] = fmaxf(acc[0] * inv + b0.x, 0.f);
    o[1] = fmaxf(acc[1] * inv + b0.y, 0.f);
    o[2] = fmaxf(acc[2] * inv + b0.z, 0.f);
    o[3] = fmaxf(acc[3] * inv + b0.w, 0.f);
    o[4] = fmaxf(acc[4] * inv + b1.x, 0.f);
    o[5] = fmaxf(acc[5] * inv + b1.y, 0.f);
    o[6] = fmaxf(acc[6] * inv + b1.z, 0.f);
    o[7] = fmaxf(acc[7] * inv + b1.w, 0.f);

    uint32_t hw[4], lw[4];
    #pragma unroll
    for (int q = 0; q < 4; q++) {
        bf16 ha = __float2bfloat16(o[q * 2]), hb = __float2bfloat16(o[q * 2 + 1]);
        __nv_bfloat162 hp(ha, hb);
        __nv_bfloat162 lp(__float2bfloat16(o[q * 2] - __bfloat162float(ha)),
                          __float2bfloat16(o[q * 2 + 1] - __bfloat162float(hb)));
        hw[q] = *(uint32_t*)&hp;
        lw[q] = *(uint32_t*)&lp;
    }
    *(uint4*)&outhi[(size_t)warp * 256 + lane * 8] =
        make_uint4(hw[0], hw[1], hw[2], hw[3]);
    *(uint4*)&outlo[(size_t)warp * 256 + lane * 8] =
        make_uint4(lw[0], lw[1], lw[2], lw[3]);

    if (AUX) {
        const float4* sT4 = (const float4*)saux;
        float ph[4];
        #pragma unroll
        for (int hh = 0; hh < 4; hh++) {
            float4 c0 = sT4[hh * 64 + lane * 2], c1 = sT4[hh * 64 + lane * 2 + 1];
            float p = o[0] * c0.x + o[1] * c0.y + o[2] * c0.z + o[3] * c0.w
                    + o[4] * c1.x + o[5] * c1.y + o[6] * c1.z + o[7] * c1.w;
            p += __shfl_xor_sync(0xffffffff, p, 16);
            p += __shfl_xor_sync(0xffffffff, p, 8);
            p += __shfl_xor_sync(0xffffffff, p, 4);
            p += __shfl_xor_sync(0xffffffff, p, 2);
            p += __shfl_xor_sync(0xffffffff, p, 1);
            ph[hh] = p;
        }
        if (lane == 0)
            ((float4*)auxout)[warp] = make_float4(ph[0], ph[1], ph[2], ph[3]);
    }
}

// ---------------------------------------------------------------------------
// Kernel wrappers
// ---------------------------------------------------------------------------
template<int NSTR, bool BIAS>
__global__ __launch_bounds__(256)
void gemm_kernel(const bf16* __restrict__ Ahi, const bf16* __restrict__ Alo,
                 const bf16* __restrict__ Bhi, const bf16* __restrict__ Blo,
                 const float* __restrict__ bias, float* __restrict__ C, int M) {
    int g = blockIdx.x;
    int mt = (M + 127) / 128;
    gemm_block<NSTR, BIAS>((g % mt) * 128, (g / mt) * 128, Ahi, Alo, Bhi, Blo,
                           bias, C, M);
}

template<int AUX>
__global__ __launch_bounds__(256)
void agg_kernel(const float* __restrict__ hs, const float* __restrict__ es,
                const float* __restrict__ ed, const int* __restrict__ rowptr,
                const int* __restrict__ csrc, const float* __restrict__ bias,
                bf16* __restrict__ outhi, bf16* __restrict__ outlo,
                const float* __restrict__ auxT, float* __restrict__ auxout,
                int Nd) {
    agg_block<AUX>(blockIdx.x, hs, es, ed, rowptr, csrc, bias, outhi, outlo,
                   auxT, auxout, Nd);
}

// fused: 1-in-9 blocks run a gemm tile, rest run agg blocks (independent work)
__global__ __launch_bounds__(256)
void fused_gemm_agg(const bf16* __restrict__ Ahi, const bf16* __restrict__ Alo,
                    const bf16* __restrict__ Bhi, const bf16* __restrict__ Blo,
                    float* __restrict__ Cg, int Mg,
                    const float* __restrict__ hs, const float* __restrict__ es,
                    const float* __restrict__ ed, const int* __restrict__ rowptr,
                    const int* __restrict__ csrc, const float* __restrict__ bias,
                    bf16* __restrict__ outhi, bf16* __restrict__ outlo,
                    const float* __restrict__ auxT, float* __restrict__ auxout,
                    int Nd) {
    int bid = blockIdx.x;
    if (bid % 9 == 0) {
        int g = bid / 9;
        int mt = (Mg + 127) / 128;
        if (g < 2 * mt)
            gemm_block<256, false>((g % mt) * 128, (g / mt) * 128, Ahi, Alo,
                                   Bhi, Blo, nullptr, Cg, Mg);
    } else {
        int a = bid - bid / 9 - 1;
        agg_block<1>(a, hs, es, ed, rowptr, csrc, bias, outhi, outlo, auxT,
                     auxout, Nd);
    }
}

// ---------------------------------------------------------------------------
// prep_smat_all: tiny attention-projection matrices, transposed [h][k]
// ---------------------------------------------------------------------------
__global__ void prep_smat_all(const float* __restrict__ Ws,
                              const float* __restrict__ Wd,
                              const float* __restrict__ as_,
                              const float* __restrict__ ad_,
                              float* __restrict__ cmbT_u,
                              float* __restrict__ cmbT_v,
                              float* __restrict__ wsatt2T,
                              float* __restrict__ vd2T) {
    int k = threadIdx.x, b = blockIdx.x;
    auto dot = [&](const float* W, const float* a, int h) {
        float s = 0.f;
        #pragma unroll 8
        for (int c = 0; c < 64; c++)
            s = fmaf(W[(size_t)k * 256 + h * 64 + c], a[h * 64 + c], s);
        return s;
    };
    if (b == 0) {
        for (int h = 0; h < 4; h++) cmbT_u[h * 256 + k] = dot(Ws, as_, h);
        for (int h = 0; h < 4; h++)
            cmbT_u[(4 + h) * 256 + k] = dot(Wd + 65536, ad_ + 256, h);
    } else if (b == 1) {
        for (int h = 0; h < 4; h++)
            cmbT_v[h * 256 + k] = dot(Ws + 65536, as_ + 256, h);
        for (int h = 0; h < 4; h++) cmbT_v[(4 + h) * 256 + k] = dot(Wd, ad_, h);
    } else if (b == 2) {
        for (int h = 0; h < 4; h++)
            wsatt2T[h * 256 + k] = dot(Ws + 3 * 65536, as_ + 3 * 256, h);
    } else {
        for (int h = 0; h < 4; h++)
            vd2T[h * 256 + k] = dot(Wd + 3 * 65536, ad_ + 3 * 256, h);
    }
}

// ---------------------------------------------------------------------------
// wconv_all: transpose+split W_src slices 0,1,3 + lin_w
// ---------------------------------------------------------------------------
__global__ void wconv_all(const float* __restrict__ W_src,
                          const float* __restrict__ lin_w,
                          bf16* __restrict__ wt_hi, bf16* __restrict__ wt_lo,
                          bf16* __restrict__ lt_hi, bf16* __restrict__ lt_lo) {
    int b = blockIdx.x, k = threadIdx.x;
    if (b < 768) {
        int sl = b >> 8, n = b & 255;
        const float* W = W_src + (size_t)(sl == 2 ? 3 : sl) * 65536;
        float f = W[(size_t)k * 256 + n];
        bf16 h = __float2bfloat16(f);
        wt_hi[((size_t)sl * 256 + n) * 256 + k] = h;
        wt_lo[((size_t)sl * 256 + n) * 256 + k] =
            __float2bfloat16(f - __bfloat162float(h));
    } else {
        int n = b - 768;
        float f = lin_w[(size_t)k * 128 + n];
        bf16 h = __float2bfloat16(f);
        lt_hi[(size_t)n * 256 + k] = h;
        lt_lo[(size_t)n * 256 + k] = __float2bfloat16(f - __bfloat162float(h));
    }
}

// ---------------------------------------------------------------------------
// splitsmall: bf16 hi/lo split of x  +  es/ed dots, one pass. Warp/node.
// ---------------------------------------------------------------------------
__global__ __launch_bounds__(256)
void splitsmall_kernel(const float* __restrict__ x, const float* __restrict__ cmbT,
                       bf16* __restrict__ hi, bf16* __restrict__ lo,
                       float* __restrict__ es, float* __restrict__ ed, int N) {
    __shared__ float sT[2048];
    for (int i = threadIdx.x; i < 2048; i += 256) sT[i] = cmbT[i];
    __syncthreads();
    int warp = (blockIdx.x * 256 + threadIdx.x) >> 5;
    int lane = threadIdx.x & 31;
    if (warp >= N) return;
    const float4* row = (const float4*)&x[(size_t)warp * 256 + lane * 8];
    float4 a0 = row[0], a1 = row[1];
    float v[8] = {a0.x, a0.y, a0.z, a0.w, a1.x, a1.y, a1.z, a1.w};

    uint32_t hw[4], lw[4];
    #pragma unroll
    for (int q = 0; q < 4; q++) {
        bf16 ha = __float2bfloat16(v[q * 2]), hb = __float2bfloat16(v[q * 2 + 1]);
        __nv_bfloat162 hp(ha, hb);
        __nv_bfloat162 lp(__float2bfloat16(v[q * 2] - __bfloat162float(ha)),
                          __float2bfloat16(v[q * 2 + 1] - __bfloat162float(hb)));
        hw[q] = *(uint32_t*)&hp;
        lw[q] = *(uint32_t*)&lp;
    }
    *(uint4*)&hi[(size_t)warp * 256 + lane * 8] = make_uint4(hw[0], hw[1], hw[2], hw[3]);
    *(uint4*)&lo[(size_t)warp * 256 + lane * 8] = make_uint4(lw[0], lw[1], lw[2], lw[3]);

    const float4* sT4 = (const float4*)sT;
    float p[8];
    #pragma unroll
    for (int h = 0; h < 8; h++) {
        float4 c0 = sT4[h * 64 + lane * 2], c1 = sT4[h * 64 + lane * 2 + 1];
        p[h] = a0.x * c0.x + a0.y * c0.y + a0.z * c0.z + a0.w * c0.w
             + a1.x * c1.x + a1.y * c1.y + a1.z * c1.z + a1.w * c1.w;
    }
    #pragma unroll
    for (int h = 0; h < 8; h++) {
        p[h] += __shfl_xor_sync(0xffffffff, p[h], 16);
        p[h] += __shfl_xor_sync(0xffffffff, p[h], 8);
        p[h] += __shfl_xor_sync(0xffffffff, p[h], 4);
        p[h] += __shfl_xor_sync(0xffffffff, p[h], 2);
        p[h] += __shfl_xor_sync(0xffffffff, p[h], 1);
    }
    if (lane == 0) {
        ((float4*)es)[warp] = make_float4(p[0], p[1], p[2], p[3]);
        ((float4*)ed)[warp] = make_float4(p[4], p[5], p[6], p[7]);
    }
}

// ---------------------------------------------------------------------------
// CSR build — both relations concatenated (dst space 100000)
// ---------------------------------------------------------------------------
__global__ void zero_kernel(int* p, int n) {
    int i = blockIdx.x * blockDim.x + threadIdx.x;
    if (i < n) p[i] = 0;
}

__global__ void count2_kernel(const int* __restrict__ euv,
                              const int* __restrict__ evu,
                              int* __restrict__ cnt) {
    int e = blockIdx.x * blockDim.x + threadIdx.x;
    if (e < NE) atomicAdd(&cnt[euv[NE + e]], 1);
    else if (e < 2 * NE) atomicAdd(&cnt[50000 + evu[NE + (e - NE)]], 1);
}

__global__ __launch_bounds__(1024)
void scan1_kernel(const int* __restrict__ in, int* __restrict__ out,
                  int* __restrict__ bsums, int n) {
    __shared__ int sh[1024];
    int i = blockIdx.x * 1024 + threadIdx.x;
    int v = (i < n) ? in[i] : 0;
    sh[threadIdx.x] = v;
    __syncthreads();
    for (int off = 1; off < 1024; off <<= 1) {
        int t = (threadIdx.x >= off) ? sh[threadIdx.x - off] : 0;
        __syncthreads();
        sh[threadIdx.x] += t;
        __syncthreads();
    }
    if (i < n) out[i] = sh[threadIdx.x] - v;
    if (threadIdx.x == 1023) bsums[blockIdx.x] = sh[1023];
}

__global__ void scan2p_kernel(int* bsums, int nb) {
    __shared__ int sh[128];
    int t = threadIdx.x;
    int v = (t < nb) ? bsums[t] : 0;
    sh[t] = v;
    __syncthreads();
    for (int off = 1; off < 128; off <<= 1) {
        int x = (t >= off) ? sh[t - off] : 0;
        __syncthreads();
        sh[t] += x;
        __syncthreads();
    }
    if (t < nb) bsums[t] = sh[t] - v;  // exclusive
}

__global__ void scan3_kernel(int* out, const int* __restrict__ bsums, int n,
                             int total) {
    int i = blockIdx.x * blockDim.x + threadIdx.x;
    if (i < n) out[i] += bsums[i >> 10];
    if (i == 0) out[n] = total;
}

__global__ void fill2_kernel(const int* __restrict__ euv,
                             const int* __restrict__ evu,
                             const int* __restrict__ rowptr,
                             int* __restrict__ cursor, int* __restrict__ csrc) {
    int e = blockIdx.x * blockDim.x + threadIdx.x;
    if (e >= 2 * NE) return;
    int s, d;
    if (e < NE) { s = euv[e]; d = euv[NE + e]; }
    else { int e2 = e - NE; s = evu[e2]; d = 50000 + evu[NE + e2]; }
    int pos = atomicAdd(&cursor[d], 1);
    csrc[rowptr[d] + pos] = s;
}

// ---------------------------------------------------------------------------
// Host
// ---------------------------------------------------------------------------
static inline void* sym(const void* s) {
    void* p = nullptr;
    cudaGetSymbolAddress(&p, s);
    return p;
}

extern "C" void kernel_launch(void* const* d_in, const int* in_sizes, int n_in,
                              void* d_out, int out_size) {
    const float* x_u   = (const float*)d_in[0];
    const float* x_v   = (const float*)d_in[1];
    const float* W_src = (const float*)d_in[2];
    const float* W_dst = (const float*)d_in[3];
    const float* att_s = (const float*)d_in[4];
    const float* att_d = (const float*)d_in[5];
    const float* bias  = (const float*)d_in[6];
    const float* lin_w = (const float*)d_in[7];
    const float* lin_b = (const float*)d_in[8];
    const int* ei_uv   = (const int*)d_in[9];
    const int* ei_vu   = (const int*)d_in[10];
    float* out = (float*)d_out;

    float *hs0 = (float*)sym(g_hs0), *hs1 = (float*)sym(g_hs1);
    bf16 *xu_hi = (bf16*)sym(g_xu_hi), *xu_lo = (bf16*)sym(g_xu_lo);
    bf16 *xv_hi = (bf16*)sym(g_xv_hi), *xv_lo = (bf16*)sym(g_xv_lo);
    bf16 *nv0_hi = (bf16*)sym(g_nv0_hi), *nv0_lo = (bf16*)sym(g_nv0_lo);
    bf16 *nu0_hi = (bf16*)sym(g_nu0_hi), *nu0_lo = (bf16*)sym(g_nu0_lo);
    bf16 *nu1_hi = (bf16*)sym(g_nu1_hi), *nu1_lo = (bf16*)sym(g_nu1_lo);
    float *es0 = (float*)sym(g_es0), *es1 = (float*)sym(g_es1), *es2 = (float*)sym(g_es2);
    float *ed0 = (float*)sym(g_ed0), *ed1 = (float*)sym(g_ed1), *ed2 = (float*)sym(g_ed2);
    float *cmbT_u = (float*)sym(g_cmbT_u), *cmbT_v = (float*)sym(g_cmbT_v);
    float *wsatt2T = (float*)sym(g_wsatt2T), *vd2T = (float*)sym(g_vd2T);
    bf16 *wt_hi = (bf16*)sym(g_wt_hi), *wt_lo = (bf16*)sym(g_wt_lo);
    bf16 *lt_hi = (bf16*)sym(g_lt_hi), *lt_lo = (bf16*)sym(g_lt_lo);
    int *rowptr = (int*)sym(g_rowptr), *csrc = (int*)sym(g_csrc);
    int *cnt = (int*)sym(g_cnt), *bsums = (int*)sym(g_bsums);

    cudaFuncSetAttribute(gemm_kernel<256, false>,
                         cudaFuncAttributeMaxDynamicSharedMemorySize, GSMEM);
    cudaFuncSetAttribute(gemm_kernel<128, true>,
                         cudaFuncAttributeMaxDynamicSharedMemorySize, GSMEM);
    cudaFuncSetAttribute(fused_gemm_agg,
                         cudaFuncAttributeMaxDynamicSharedMemorySize, GSMEM);

    const size_t WSZ = 256 * 256, BSZ = 256;
    const int NB = (NALL + 1023) / 1024;  // 98 scan blocks

    // 0: tiny attention matrices
    prep_smat_all<<<4, 256>>>(W_src, W_dst, att_s, att_d,
                              cmbT_u, cmbT_v, wsatt2T, vd2T);
    // 1: weight convert
    wconv_all<<<896, 256>>>(W_src, lin_w, wt_hi, wt_lo, lt_hi, lt_lo);
    // 2: split + es0/ed1 for x_u
    splitsmall_kernel<<<6250, 256>>>(x_u, cmbT_u, xu_hi, xu_lo, es0, ed1, NU);
    // 3: gemm0 -> hs0   (ncu capture index)
    gemm_kernel<256, false><<<782, 256, GSMEM>>>(
        xu_hi, xu_lo, wt_hi + 0 * WSZ, wt_lo + 0 * WSZ, nullptr, hs0, NU);
    // 4: split + es1/ed0 for x_v
    splitsmall_kernel<<<6250, 256>>>(x_v, cmbT_v, xv_hi, xv_lo, es1, ed0, NV);
    // 5-11: CSR (both relations concatenated)
    zero_kernel<<<(NALL + 255) / 256, 256>>>(cnt, NALL);
    count2_kernel<<<(2 * NE + 255) / 256, 256>>>(ei_uv, ei_vu, cnt);
    scan1_kernel<<<NB, 1024>>>(cnt, rowptr, bsums, NALL);
    scan2p_kernel<<<1, 128>>>(bsums, NB);
    scan3_kernel<<<(NALL + 255) / 256, 256>>>(rowptr, bsums, NALL, 2 * NE);
    zero_kernel<<<(NALL + 255) / 256, 256>>>(cnt, NALL);
    fill2_kernel<<<(2 * NE + 255) / 256, 256>>>(ei_uv, ei_vu, rowptr, cnt, csrc);

    // 12: agg0 (hs0 -> nv0, +es2)  ||  gemm1 (xv -> hs1)
    fused_gemm_agg<<<FUSED_T, 256, GSMEM>>>(
        xv_hi, xv_lo, wt_hi + 1 * WSZ, wt_lo + 1 * WSZ, hs1, NV,
        hs0, es0, ed0, rowptr, csrc, bias + 0 * BSZ,
        nv0_hi, nv0_lo, wsatt2T, es2, NV);
    // 13: agg1 (hs1 -> nu0, +ed2)  ||  gemm2 (nv0 -> hs0)
    fused_gemm_agg<<<FUSED_T, 256, GSMEM>>>(
        nv0_hi, nv0_lo, wt_hi + 2 * WSZ, wt_lo + 2 * WSZ, hs0, NV,
        hs1, es1, ed1, rowptr + 50000, csrc, bias + 1 * BSZ,
        nu0_hi, nu0_lo, vd2T, ed2, NU);
    // 14: agg2 (hs0 -> nu1)
    agg_kernel<0><<<6250, 256>>>(hs0, es2, ed2, rowptr + 50000, csrc,
                                 bias + 3 * BSZ, nu1_hi, nu1_lo,
                                 nullptr, nullptr, NU);
    // 15: final linear
    gemm_kernel<128, true><<<391, 256, GSMEM>>>(
        nu1_hi, nu1_lo, lt_hi, lt_lo, lin_b, out, NU);
}

// round 11
// speedup vs baseline: 1.2104x; 1.2104x over previous
#include <cuda_runtime.h>
#include <cuda_bf16.h>
#include <cstdint>

typedef __nv_bfloat16 bf16;

static const int NU = 50000;
static const int NV = 50000;
static const int NE = 500000;
static const int NALL = 100000;          // concatenated dst-node space
#define NEG_SLOPE 0.2f
#define EPS_F 1e-16f
#define GSMEM 81920

// ---------------------------------------------------------------------------
// Static device scratch
// ---------------------------------------------------------------------------
__device__ __align__(128) float g_hs0[50048 * 256];
__device__ __align__(128) float g_hs1[50048 * 256];
__device__ __align__(128) bf16 g_xu_hi[50048 * 256], g_xu_lo[50048 * 256];
__device__ __align__(128) bf16 g_xv_hi[50048 * 256], g_xv_lo[50048 * 256];
__device__ __align__(128) bf16 g_nv0_hi[50048 * 256], g_nv0_lo[50048 * 256];
__device__ __align__(128) bf16 g_nu0_hi[50048 * 256], g_nu0_lo[50048 * 256];
__device__ __align__(128) bf16 g_nu1_hi[50048 * 256], g_nu1_lo[50048 * 256];
__device__ __align__(128) float g_es0[50048 * 4], g_es1[50048 * 4], g_es2[50048 * 4];
__device__ __align__(128) float g_ed0[50048 * 4], g_ed1[50048 * 4], g_ed2[50048 * 4];
__device__ __align__(128) float g_cmbT_u[8 * 256], g_cmbT_v[8 * 256];
__device__ __align__(128) float g_wsatt2T[4 * 256], g_vd2T[4 * 256];
__device__ __align__(128) bf16 g_wt_hi[3 * 256 * 256], g_wt_lo[3 * 256 * 256];
__device__ __align__(128) bf16 g_lt_hi[128 * 256], g_lt_lo[128 * 256];
__device__ __align__(128) int g_rowptr[100001];
__device__ __align__(128) int g_csrc[1000000];
__device__ __align__(128) int g_cnt[100001], g_bsums[128];

// ---------------------------------------------------------------------------
// helpers
// ---------------------------------------------------------------------------
__device__ __forceinline__ uint32_t smem_u32(const void* p) {
    uint32_t a;
    asm("{ .reg .u64 t; cvta.to.shared.u64 t, %1; cvt.u32.u64 %0, t; }"
        : "=r"(a) : "l"(p));
    return a;
}

__device__ __forceinline__ void cp16(uint32_t dst, const void* src) {
    asm volatile("cp.async.cg.shared.global [%0], [%1], 16;"
                 :: "r"(dst), "l"(src));
}

__device__ __forceinline__ void ldsm4(uint32_t& r0, uint32_t& r1, uint32_t& r2,
                                      uint32_t& r3, uint32_t addr) {
    asm volatile("ldmatrix.sync.aligned.m8n8.x4.shared.b16 {%0,%1,%2,%3}, [%4];"
                 : "=r"(r0), "=r"(r1), "=r"(r2), "=r"(r3) : "r"(addr));
}

__device__ __forceinline__ void mma_bf16(float* c, const uint32_t* a,
                                         const uint32_t* b) {
    asm volatile(
        "mma.sync.aligned.m16n8k16.row.col.f32.bf16.bf16.f32 "
        "{%0,%1,%2,%3}, {%4,%5,%6,%7}, {%8,%9}, {%0,%1,%2,%3};"
        : "+f"(c[0]), "+f"(c[1]), "+f"(c[2]), "+f"(c[3])
        : "r"(a[0]), "r"(a[1]), "r"(a[2]), "r"(a[3]), "r"(b[0]), "r"(b[1]));
}

// ---------------------------------------------------------------------------
// GEMM: C[M,NSTR] = (Ahi+Alo)@(Bhi+Blo)^T, 2-stage cp.async, 1 sync/k-iter
// (exactly the R6-proven kernel)
// ---------------------------------------------------------------------------
template<int NSTR, bool BIAS>
__global__ __launch_bounds__(256)
void gemm_kernel(const bf16* __restrict__ Ahi, const bf16* __restrict__ Alo,
                 const bf16* __restrict__ Bhi, const bf16* __restrict__ Blo,
                 const float* __restrict__ bias, float* __restrict__ C, int M) {
    extern __shared__ __align__(128) char smg[];
    const uint32_t sb = smem_u32(smg);
    const int tid = threadIdx.x, lane = tid & 31, wid = tid >> 5;
    const int wm = wid >> 2, wn = wid & 3;
    const int mt = (M + 127) / 128;
    const int bm = (blockIdx.x % mt) * 128, bn = (blockIdx.x / mt) * 128;

    const char* src[4] = {
        (const char*)(Ahi + (size_t)bm * 256), (const char*)(Alo + (size_t)bm * 256),
        (const char*)(Bhi + (size_t)bn * 256), (const char*)(Blo + (size_t)bn * 256)};

    uint32_t aBH[4], aBL[4], bBH[2], bBL[2];
    {
        int ar = wm * 64 + (lane & 15), ac = (lane >> 4) * 8;
        #pragma unroll
        for (int i = 0; i < 4; i++) {
            aBH[i] = sb + (uint32_t)(ar + i * 16) * 80 + ac * 2;
            aBL[i] = aBH[i] + 10240;
        }
        int br = wn * 32 + ((lane >> 4) << 3) + (lane & 7);
        int bc = ((lane >> 3) & 1) * 8;
        #pragma unroll
        for (int p = 0; p < 2; p++) {
            bBH[p] = sb + 20480 + (uint32_t)(br + p * 16) * 80 + bc * 2;
            bBL[p] = bBH[p] + 10240;
        }
    }

    float acc[4][4][4];
    #pragma unroll
    for (int i = 0; i < 4; i++)
        #pragma unroll
        for (int j = 0; j < 4; j++)
            #pragma unroll
            for (int q = 0; q < 4; q++) acc[i][j][q] = 0.f;

    auto load_stage = [&](int kc, int buf) {
        #pragma unroll
        for (int arr = 0; arr < 4; arr++) {
            const char* s = src[arr] + kc * 64;
            uint32_t d = sb + buf * 40960 + arr * 10240;
            #pragma unroll
            for (int t2 = 0; t2 < 2; t2++) {
                int cid = t2 * 256 + tid, row = cid >> 2, c = cid & 3;
                cp16(d + row * 80 + c * 16, s + (size_t)row * 512 + c * 16);
            }
        }
        asm volatile("cp.async.commit_group;");
    };

    load_stage(0, 0);
    for (int kc = 0; kc < 8; kc++) {
        int buf = kc & 1;
        asm volatile("cp.async.wait_group 0;");
        __syncthreads();
        if (kc < 7) load_stage(kc + 1, buf ^ 1);
        uint32_t bo = (uint32_t)buf * 40960;
        #pragma unroll
        for (int ks = 0; ks < 2; ks++) {
            uint32_t ah[4][4], al[4][4], bh[4][2], bl[4][2];
            #pragma unroll
            for (int i = 0; i < 4; i++) {
                ldsm4(ah[i][0], ah[i][1], ah[i][2], ah[i][3], aBH[i] + bo + ks * 32);
                ldsm4(al[i][0], al[i][1], al[i][2], al[i][3], aBL[i] + bo + ks * 32);
            }
            #pragma unroll
            for (int p = 0; p < 2; p++) {
                uint32_t r0, r1, r2, r3;
                ldsm4(r0, r1, r2, r3, bBH[p] + bo + ks * 32);
                bh[p * 2][0] = r0; bh[p * 2][1] = r1;
                bh[p * 2 + 1][0] = r2; bh[p * 2 + 1][1] = r3;
                ldsm4(r0, r1, r2, r3, bBL[p] + bo + ks * 32);
                bl[p * 2][0] = r0; bl[p * 2][1] = r1;
                bl[p * 2 + 1][0] = r2; bl[p * 2 + 1][1] = r3;
            }
            #pragma unroll
            for (int i = 0; i < 4; i++)
                #pragma unroll
                for (int j = 0; j < 4; j++) {
                    mma_bf16(acc[i][j], ah[i], bh[j]);
                    mma_bf16(acc[i][j], ah[i], bl[j]);
                    mma_bf16(acc[i][j], al[i], bh[j]);
                }
        }
    }

    #pragma unroll
    for (int i = 0; i < 4; i++) {
        int r0 = bm + wm * 64 + i * 16 + (lane >> 2);
        #pragma unroll
        for (int j = 0; j < 4; j++) {
            int cc = bn + wn * 32 + j * 8 + 2 * (lane & 3);
            float b0 = 0.f, b1 = 0.f;
            if (BIAS) { b0 = __ldg(&bias[cc]); b1 = __ldg(&bias[cc + 1]); }
            if (r0 < M)
                *(float2*)&C[(size_t)r0 * NSTR + cc] =
                    make_float2(acc[i][j][0] + b0, acc[i][j][1] + b1);
            if (r0 + 8 < M)
                *(float2*)&C[(size_t)(r0 + 8) * NSTR + cc] =
                    make_float2(acc[i][j][2] + b0, acc[i][j][3] + b1);
        }
    }
}

// ---------------------------------------------------------------------------
// Aggregation (warp/node): softmax + gather + bias + relu, bf16 hi/lo out.
// AUX=1: auxout[n,h] = out_row . auxT[h]   (exactly the R6-proven kernel)
// ---------------------------------------------------------------------------
template<int AUX>
__global__ __launch_bounds__(256)
void agg_kernel(const float* __restrict__ hs, const float* __restrict__ es,
                const float* __restrict__ ed, const int* __restrict__ rowptr,
                const int* __restrict__ csrc, const float* __restrict__ bias,
                bf16* __restrict__ outhi, bf16* __restrict__ outlo,
                const float* __restrict__ auxT, float* __restrict__ auxout,
                int Nd) {
    __shared__ float saux[1024];
    if (AUX) {
        for (int i = threadIdx.x; i < 1024; i += 256) saux[i] = auxT[i];
        __syncthreads();
    }
    int warp = blockIdx.x * 8 + (threadIdx.x >> 5);
    int lane = threadIdx.x & 31;
    if (warp >= Nd) return;
    int h = lane >> 3;
    float edh = ed[warp * 4 + h];
    int beg = rowptr[warp], end = rowptr[warp + 1];
    float denom = 0.f;
    float acc[8] = {0.f, 0.f, 0.f, 0.f, 0.f, 0.f, 0.f, 0.f};
    int e = beg;
    for (; e + 2 <= end; e += 2) {
        int s0 = csrc[e], s1 = csrc[e + 1];
        float a0 = es[s0 * 4 + h] + edh;
        float a1 = es[s1 * 4 + h] + edh;
        a0 = (a0 > 0.f) ? a0 : a0 * NEG_SLOPE;
        a1 = (a1 > 0.f) ? a1 : a1 * NEG_SLOPE;
        float w0 = __expf(a0), w1 = __expf(a1);
        denom += w0 + w1;
        const float4* r0 = (const float4*)&hs[(size_t)s0 * 256 + lane * 8];
        const float4* r1 = (const float4*)&hs[(size_t)s1 * 256 + lane * 8];
        float4 p0 = r0[0], p1 = r0[1], q0 = r1[0], q1 = r1[1];
        acc[0] = fmaf(w0, p0.x, acc[0]); acc[1] = fmaf(w0, p0.y, acc[1]);
        acc[2] = fmaf(w0, p0.z, acc[2]); acc[3] = fmaf(w0, p0.w, acc[3]);
        acc[4] = fmaf(w0, p1.x, acc[4]); acc[5] = fmaf(w0, p1.y, acc[5]);
        acc[6] = fmaf(w0, p1.z, acc[6]); acc[7] = fmaf(w0, p1.w, acc[7]);
        acc[0] = fmaf(w1, q0.x, acc[0]); acc[1] = fmaf(w1, q0.y, acc[1]);
        acc[2] = fmaf(w1, q0.z, acc[2]); acc[3] = fmaf(w1, q0.w, acc[3]);
        acc[4] = fmaf(w1, q1.x, acc[4]); acc[5] = fmaf(w1, q1.y, acc[5]);
        acc[6] = fmaf(w1, q1.z, acc[6]); acc[7] = fmaf(w1, q1.w, acc[7]);
    }
    if (e < end) {
        int s = csrc[e];
        float a = es[s * 4 + h] + edh;
        a = (a > 0.f) ? a : a * NEG_SLOPE;
        float w = __expf(a);
        denom += w;
        const float4* r = (const float4*)&hs[(size_t)s * 256 + lane * 8];
        float4 v0 = r[0], v1 = r[1];
        acc[0] = fmaf(w, v0.x, acc[0]); acc[1] = fmaf(w, v0.y, acc[1]);
        acc[2] = fmaf(w, v0.z, acc[2]); acc[3] = fmaf(w, v0.w, acc[3]);
        acc[4] = fmaf(w, v1.x, acc[4]); acc[5] = fmaf(w, v1.y, acc[5]);
        acc[6] = fmaf(w, v1.z, acc[6]); acc[7] = fmaf(w, v1.w, acc[7]);
    }
    float inv = 1.f / (denom + EPS_F);
    const float4* bp = (const float4*)&bias[lane * 8];
    float4 b0 = bp[0], b1 = bp[1];
    float o[8];
    o[0] = fmaxf(acc[0] * inv + b0.x, 0.f);
    o[1] = fmaxf(acc[1] * inv + b0.y, 0.f);
    o[2] = fmaxf(acc[2] * inv + b0.z, 0.f);
    o[3] = fmaxf(acc[3] * inv + b0.w, 0.f);
    o[4] = fmaxf(acc[4] * inv + b1.x, 0.f);
    o[5] = fmaxf(acc[5] * inv + b1.y, 0.f);
    o[6] = fmaxf(acc[6] * inv + b1.z, 0.f);
    o[7] = fmaxf(acc[7] * inv + b1.w, 0.f);

    uint32_t hw[4], lw[4];
    #pragma unroll
    for (int q = 0; q < 4; q++) {
        bf16 ha = __float2bfloat16(o[q * 2]), hb = __float2bfloat16(o[q * 2 + 1]);
        __nv_bfloat162 hp(ha, hb);
        __nv_bfloat162 lp(__float2bfloat16(o[q * 2] - __bfloat162float(ha)),
                          __float2bfloat16(o[q * 2 + 1] - __bfloat162float(hb)));
        hw[q] = *(uint32_t*)&hp;
        lw[q] = *(uint32_t*)&lp;
    }
    *(uint4*)&outhi[(size_t)warp * 256 + lane * 8] =
        make_uint4(hw[0], hw[1], hw[2], hw[3]);
    *(uint4*)&outlo[(size_t)warp * 256 + lane * 8] =
        make_uint4(lw[0], lw[1], lw[2], lw[3]);

    if (AUX) {
        const float4* sT4 = (const float4*)saux;
        float ph[4];
        #pragma unroll
        for (int hh = 0; hh < 4; hh++) {
            float4 c0 = sT4[hh * 64 + lane * 2], c1 = sT4[hh * 64 + lane * 2 + 1];
            float p = o[0] * c0.x + o[1] * c0.y + o[2] * c0.z + o[3] * c0.w
                    + o[4] * c1.x + o[5] * c1.y + o[6] * c1.z + o[7] * c1.w;
            p += __shfl_xor_sync(0xffffffff, p, 16);
            p += __shfl_xor_sync(0xffffffff, p, 8);
            p += __shfl_xor_sync(0xffffffff, p, 4);
            p += __shfl_xor_sync(0xffffffff, p, 2);
            p += __shfl_xor_sync(0xffffffff, p, 1);
            ph[hh] = p;
        }
        if (lane == 0)
            ((float4*)auxout)[warp] = make_float4(ph[0], ph[1], ph[2], ph[3]);
    }
}

// ---------------------------------------------------------------------------
// prep_smat_all / wconv_all / splitsmall  (R6-proven standalone kernels)
// ---------------------------------------------------------------------------
__global__ void prep_smat_all(const float* __restrict__ Ws,
                              const float* __restrict__ Wd,
                              const float* __restrict__ as_,
                              const float* __restrict__ ad_,
                              float* __restrict__ cmbT_u,
                              float* __restrict__ cmbT_v,
                              float* __restrict__ wsatt2T,
                              float* __restrict__ vd2T) {
    int k = threadIdx.x, b = blockIdx.x;
    auto dot = [&](const float* W, const float* a, int h) {
        float s = 0.f;
        #pragma unroll 8
        for (int c = 0; c < 64; c++)
            s = fmaf(W[(size_t)k * 256 + h * 64 + c], a[h * 64 + c], s);
        return s;
    };
    if (b == 0) {
        for (int h = 0; h < 4; h++) cmbT_u[h * 256 + k] = dot(Ws, as_, h);
        for (int h = 0; h < 4; h++)
            cmbT_u[(4 + h) * 256 + k] = dot(Wd + 65536, ad_ + 256, h);
    } else if (b == 1) {
        for (int h = 0; h < 4; h++)
            cmbT_v[h * 256 + k] = dot(Ws + 65536, as_ + 256, h);
        for (int h = 0; h < 4; h++) cmbT_v[(4 + h) * 256 + k] = dot(Wd, ad_, h);
    } else if (b == 2) {
        for (int h = 0; h < 4; h++)
            wsatt2T[h * 256 + k] = dot(Ws + 3 * 65536, as_ + 3 * 256, h);
    } else {
        for (int h = 0; h < 4; h++)
            vd2T[h * 256 + k] = dot(Wd + 3 * 65536, ad_ + 3 * 256, h);
    }
}

__global__ void wconv_all(const float* __restrict__ W_src,
                          const float* __restrict__ lin_w,
                          bf16* __restrict__ wt_hi, bf16* __restrict__ wt_lo,
                          bf16* __restrict__ lt_hi, bf16* __restrict__ lt_lo) {
    int b = blockIdx.x, k = threadIdx.x;
    if (b < 768) {
        int sl = b >> 8, n = b & 255;
        const float* W = W_src + (size_t)(sl == 2 ? 3 : sl) * 65536;
        float f = W[(size_t)k * 256 + n];
        bf16 h = __float2bfloat16(f);
        wt_hi[((size_t)sl * 256 + n) * 256 + k] = h;
        wt_lo[((size_t)sl * 256 + n) * 256 + k] =
            __float2bfloat16(f - __bfloat162float(h));
    } else {
        int n = b - 768;
        float f = lin_w[(size_t)k * 128 + n];
        bf16 h = __float2bfloat16(f);
        lt_hi[(size_t)n * 256 + k] = h;
        lt_lo[(size_t)n * 256 + k] = __float2bfloat16(f - __bfloat162float(h));
    }
}

__global__ __launch_bounds__(256)
void splitsmall_kernel(const float* __restrict__ x, const float* __restrict__ cmbT,
                       bf16* __restrict__ hi, bf16* __restrict__ lo,
                       float* __restrict__ es, float* __restrict__ ed, int N) {
    __shared__ float sT[2048];
    for (int i = threadIdx.x; i < 2048; i += 256) sT[i] = cmbT[i];
    __syncthreads();
    int warp = (blockIdx.x * 256 + threadIdx.x) >> 5;
    int lane = threadIdx.x & 31;
    if (warp >= N) return;
    const float4* row = (const float4*)&x[(size_t)warp * 256 + lane * 8];
    float4 a0 = row[0], a1 = row[1];
    float v[8] = {a0.x, a0.y, a0.z, a0.w, a1.x, a1.y, a1.z, a1.w};

    uint32_t hw[4], lw[4];
    #pragma unroll
    for (int q = 0; q < 4; q++) {
        bf16 ha = __float2bfloat16(v[q * 2]), hb = __float2bfloat16(v[q * 2 + 1]);
        __nv_bfloat162 hp(ha, hb);
        __nv_bfloat162 lp(__float2bfloat16(v[q * 2] - __bfloat162float(ha)),
                          __float2bfloat16(v[q * 2 + 1] - __bfloat162float(hb)));
        hw[q] = *(uint32_t*)&hp;
        lw[q] = *(uint32_t*)&lp;
    }
    *(uint4*)&hi[(size_t)warp * 256 + lane * 8] = make_uint4(hw[0], hw[1], hw[2], hw[3]);
    *(uint4*)&lo[(size_t)warp * 256 + lane * 8] = make_uint4(lw[0], lw[1], lw[2], lw[3]);

    const float4* sT4 = (const float4*)sT;
    float p[8];
    #pragma unroll
    for (int h = 0; h < 8; h++) {
        float4 c0 = sT4[h * 64 + lane * 2], c1 = sT4[h * 64 + lane * 2 + 1];
        p[h] = a0.x * c0.x + a0.y * c0.y + a0.z * c0.z + a0.w * c0.w
             + a1.x * c1.x + a1.y * c1.y + a1.z * c1.z + a1.w * c1.w;
    }
    #pragma unroll
    for (int h = 0; h < 8; h++) {
        p[h] += __shfl_xor_sync(0xffffffff, p[h], 16);
        p[h] += __shfl_xor_sync(0xffffffff, p[h], 8);
        p[h] += __shfl_xor_sync(0xffffffff, p[h], 4);
        p[h] += __shfl_xor_sync(0xffffffff, p[h], 2);
        p[h] += __shfl_xor_sync(0xffffffff, p[h], 1);
    }
    if (lane == 0) {
        ((float4*)es)[warp] = make_float4(p[0], p[1], p[2], p[3]);
        ((float4*)ed)[warp] = make_float4(p[4], p[5], p[6], p[7]);
    }
}

// ---------------------------------------------------------------------------
// CSR build — both relations concatenated (R6-proven kernels)
// ---------------------------------------------------------------------------
__global__ void zero_kernel(int* p, int n) {
    int i = blockIdx.x * blockDim.x + threadIdx.x;
    if (i < n) p[i] = 0;
}

__global__ void count2_kernel(const int* __restrict__ euv,
                              const int* __restrict__ evu,
                              int* __restrict__ cnt) {
    int e = blockIdx.x * blockDim.x + threadIdx.x;
    if (e < NE) atomicAdd(&cnt[euv[NE + e]], 1);
    else if (e < 2 * NE) atomicAdd(&cnt[50000 + evu[NE + (e - NE)]], 1);
}

__global__ __launch_bounds__(1024)
void scan1_kernel(const int* __restrict__ in, int* __restrict__ out,
                  int* __restrict__ bsums, int n) {
    __shared__ int sh[1024];
    int i = blockIdx.x * 1024 + threadIdx.x;
    int v = (i < n) ? in[i] : 0;
    sh[threadIdx.x] = v;
    __syncthreads();
    for (int off = 1; off < 1024; off <<= 1) {
        int t = (threadIdx.x >= off) ? sh[threadIdx.x - off] : 0;
        __syncthreads();
        sh[threadIdx.x] += t;
        __syncthreads();
    }
    if (i < n) out[i] = sh[threadIdx.x] - v;
    if (threadIdx.x == 1023) bsums[blockIdx.x] = sh[1023];
}

__global__ void scan2p_kernel(int* bsums, int nb) {
    __shared__ int sh[128];
    int t = threadIdx.x;
    int v = (t < nb) ? bsums[t] : 0;
    sh[t] = v;
    __syncthreads();
    for (int off = 1; off < 128; off <<= 1) {
        int x = (t >= off) ? sh[t - off] : 0;
        __syncthreads();
        sh[t] += x;
        __syncthreads();
    }
    if (t < nb) bsums[t] = sh[t] - v;   // exclusive
}

__global__ void scan3_kernel(int* out, const int* __restrict__ bsums, int n,
                             int total) {
    int i = blockIdx.x * blockDim.x + threadIdx.x;
    if (i < n) out[i] += bsums[i >> 10];
    if (i == 0) out[n] = total;
}

__global__ void fill2_kernel(const int* __restrict__ euv,
                             const int* __restrict__ evu,
                             const int* __restrict__ rowptr,
                             int* __restrict__ cursor, int* __restrict__ csrc) {
    int e = blockIdx.x * blockDim.x + threadIdx.x;
    if (e >= 2 * NE) return;
    int s, d;
    if (e < NE) { s = euv[e]; d = euv[NE + e]; }
    else { int e2 = e - NE; s = evu[e2]; d = 50000 + evu[NE + e2]; }
    int pos = atomicAdd(&cursor[d], 1);
    csrc[rowptr[d] + pos] = s;
}

// ---------------------------------------------------------------------------
// Host — single stream, plain launches only
// ---------------------------------------------------------------------------
static inline void* sym(const void* s) {
    void* p = nullptr;
    cudaGetSymbolAddress(&p, s);
    return p;
}

extern "C" void kernel_launch(void* const* d_in, const int* in_sizes, int n_in,
                              void* d_out, int out_size) {
    const float* x_u   = (const float*)d_in[0];
    const float* x_v   = (const float*)d_in[1];
    const float* W_src = (const float*)d_in[2];
    const float* W_dst = (const float*)d_in[3];
    const float* att_s = (const float*)d_in[4];
    const float* att_d = (const float*)d_in[5];
    const float* bias  = (const float*)d_in[6];
    const float* lin_w = (const float*)d_in[7];
    const float* lin_b = (const float*)d_in[8];
    const int* ei_uv   = (const int*)d_in[9];
    const int* ei_vu   = (const int*)d_in[10];
    float* out = (float*)d_out;

    float *hs0 = (float*)sym(g_hs0), *hs1 = (float*)sym(g_hs1);
    bf16 *xu_hi = (bf16*)sym(g_xu_hi), *xu_lo = (bf16*)sym(g_xu_lo);
    bf16 *xv_hi = (bf16*)sym(g_xv_hi), *xv_lo = (bf16*)sym(g_xv_lo);
    bf16 *nv0_hi = (bf16*)sym(g_nv0_hi), *nv0_lo = (bf16*)sym(g_nv0_lo);
    bf16 *nu0_hi = (bf16*)sym(g_nu0_hi), *nu0_lo = (bf16*)sym(g_nu0_lo);
    bf16 *nu1_hi = (bf16*)sym(g_nu1_hi), *nu1_lo = (bf16*)sym(g_nu1_lo);
    float *es0 = (float*)sym(g_es0), *es1 = (float*)sym(g_es1), *es2 = (float*)sym(g_es2);
    float *ed0 = (float*)sym(g_ed0), *ed1 = (float*)sym(g_ed1), *ed2 = (float*)sym(g_ed2);
    float *cmbT_u = (float*)sym(g_cmbT_u), *cmbT_v = (float*)sym(g_cmbT_v);
    float *wsatt2T = (float*)sym(g_wsatt2T), *vd2T = (float*)sym(g_vd2T);
    bf16 *wt_hi = (bf16*)sym(g_wt_hi), *wt_lo = (bf16*)sym(g_wt_lo);
    bf16 *lt_hi = (bf16*)sym(g_lt_hi), *lt_lo = (bf16*)sym(g_lt_lo);
    int *rowptr = (int*)sym(g_rowptr), *csrc = (int*)sym(g_csrc);
    int *cnt = (int*)sym(g_cnt), *bsums = (int*)sym(g_bsums);

    cudaFuncSetAttribute(gemm_kernel<256, false>,
                         cudaFuncAttributeMaxDynamicSharedMemorySize, GSMEM);
    cudaFuncSetAttribute(gemm_kernel<128, true>,
                         cudaFuncAttributeMaxDynamicSharedMemorySize, GSMEM);

    const size_t WSZ = 256 * 256, BSZ = 256;
    const int NB = (NALL + 1023) / 1024;   // 98

    // L0: tiny attention matrices
    prep_smat_all<<<4, 256>>>(W_src, W_dst, att_s, att_d,
                              cmbT_u, cmbT_v, wsatt2T, vd2T);
    // L1: weight convert
    wconv_all<<<896, 256>>>(W_src, lin_w, wt_hi, wt_lo, lt_hi, lt_lo);
    // L2: split + es0/ed1 for x_u
    splitsmall_kernel<<<6250, 256>>>(x_u, cmbT_u, xu_hi, xu_lo, es0, ed1, NU);
    // L3: gemm0 -> hs0   (ncu capture index)
    gemm_kernel<256, false><<<782, 256, GSMEM>>>(
        xu_hi, xu_lo, wt_hi + 0 * WSZ, wt_lo + 0 * WSZ, nullptr, hs0, NU);
    // L4: split + es1/ed0 for x_v
    splitsmall_kernel<<<6250, 256>>>(x_v, cmbT_v, xv_hi, xv_lo, es1, ed0, NV);
    // L5-L11: CSR (both relations concatenated)
    zero_kernel<<<(NALL + 255) / 256, 256>>>(cnt, NALL);
    count2_kernel<<<(2 * NE + 255) / 256, 256>>>(ei_uv, ei_vu, cnt);
    scan1_kernel<<<NB, 1024>>>(cnt, rowptr, bsums, NALL);
    scan2p_kernel<<<1, 128>>>(bsums, NB);
    scan3_kernel<<<(NALL + 255) / 256, 256>>>(rowptr, bsums, NALL, 2 * NE);
    zero_kernel<<<(NALL + 255) / 256, 256>>>(cnt, NALL);
    fill2_kernel<<<(2 * NE + 255) / 256, 256>>>(ei_uv, ei_vu, rowptr, cnt, csrc);

    // L12: agg0 (hs0 -> nv0, +es2)
    agg_kernel<1><<<6250, 256>>>(hs0, es0, ed0, rowptr, csrc, bias + 0 * BSZ,
                                 nv0_hi, nv0_lo, wsatt2T, es2, NV);
    // L13: gemm1 (xv -> hs1)
    gemm_kernel<256, false><<<782, 256, GSMEM>>>(
        xv_hi, xv_lo, wt_hi + 1 * WSZ, wt_lo + 1 * WSZ, nullptr, hs1, NV);
    // L14: agg1 (hs1 -> nu0, +ed2)
    agg_kernel<1><<<6250, 256>>>(hs1, es1, ed1, rowptr + 50000, csrc,
                                 bias + 1 * BSZ, nu0_hi, nu0_lo, vd2T, ed2, NU);
    // L15: gemm2 (nv0 -> hs0)
    gemm_kernel<256, false><<<782, 256, GSMEM>>>(
        nv0_hi, nv0_lo, wt_hi + 2 * WSZ, wt_lo + 2 * WSZ, nullptr, hs0, NV);
    // L16: agg2 (hs0 -> nu1)
    agg_kernel<0><<<6250, 256>>>(hs0, es2, ed2, rowptr + 50000, csrc,
                                 bias + 3 * BSZ, nu1_hi, nu1_lo,
                                 nullptr, nullptr, NU);
    // L17: final linear
    gemm_kernel<128, true><<<391, 256, GSMEM>>>(
        nu1_hi, nu1_lo, lt_hi, lt_lo, lin_b, out, NU);
}

// round 13
// speedup vs baseline: 1.3169x; 1.0880x over previous
#include <cuda_runtime.h>
#include <cuda_bf16.h>
#include <cuda_fp16.h>
#include <cstdint>

typedef __nv_bfloat16 bf16;

static const int NU = 50000;
static const int NV = 50000;
static const int NE = 500000;
static const int NALL = 100000;          // concatenated dst-node space
#define NEG_SLOPE 0.2f
#define EPS_F 1e-16f
#define GSMEM 81920

// ---------------------------------------------------------------------------
// Static device scratch
// ---------------------------------------------------------------------------
__device__ __align__(128) __half g_hs0[50048 * 256];
__device__ __align__(128) __half g_hs1[50048 * 256];
__device__ __align__(128) bf16 g_xu_hi[50048 * 256], g_xu_lo[50048 * 256];
__device__ __align__(128) bf16 g_xv_hi[50048 * 256], g_xv_lo[50048 * 256];
__device__ __align__(128) bf16 g_nv0_hi[50048 * 256], g_nv0_lo[50048 * 256];
__device__ __align__(128) bf16 g_nu0_hi[50048 * 256], g_nu0_lo[50048 * 256];
__device__ __align__(128) bf16 g_nu1_hi[50048 * 256], g_nu1_lo[50048 * 256];
__device__ __align__(128) float g_es0[50048 * 4], g_es1[50048 * 4], g_es2[50048 * 4];
__device__ __align__(128) float g_ed0[50048 * 4], g_ed1[50048 * 4], g_ed2[50048 * 4];
__device__ __align__(128) float g_cmbT_u[8 * 256], g_cmbT_v[8 * 256];
__device__ __align__(128) float g_wsatt2T[4 * 256], g_vd2T[4 * 256];
__device__ __align__(128) bf16 g_wt_hi[3 * 256 * 256], g_wt_lo[3 * 256 * 256];
__device__ __align__(128) bf16 g_lt_hi[128 * 256], g_lt_lo[128 * 256];
__device__ __align__(128) int g_rowptr[100001];
__device__ __align__(128) int g_csrc[1000000];
__device__ __align__(128) int g_cnt[100001], g_bsums[128];

// ---------------------------------------------------------------------------
// helpers
// ---------------------------------------------------------------------------
__device__ __forceinline__ uint32_t smem_u32(const void* p) {
    uint32_t a;
    asm("{ .reg .u64 t; cvta.to.shared.u64 t, %1; cvt.u32.u64 %0, t; }"
        : "=r"(a) : "l"(p));
    return a;
}

__device__ __forceinline__ void cp16(uint32_t dst, const void* src) {
    asm volatile("cp.async.cg.shared.global [%0], [%1], 16;"
                 :: "r"(dst), "l"(src));
}

__device__ __forceinline__ void ldsm4(uint32_t& r0, uint32_t& r1, uint32_t& r2,
                                      uint32_t& r3, uint32_t addr) {
    asm volatile("ldmatrix.sync.aligned.m8n8.x4.shared.b16 {%0,%1,%2,%3}, [%4];"
                 : "=r"(r0), "=r"(r1), "=r"(r2), "=r"(r3) : "r"(addr));
}

__device__ __forceinline__ void mma_bf16(float* c, const uint32_t* a,
                                         const uint32_t* b) {
    asm volatile(
        "mma.sync.aligned.m16n8k16.row.col.f32.bf16.bf16.f32 "
        "{%0,%1,%2,%3}, {%4,%5,%6,%7}, {%8,%9}, {%0,%1,%2,%3};"
        : "+f"(c[0]), "+f"(c[1]), "+f"(c[2]), "+f"(c[3])
        : "r"(a[0]), "r"(a[1]), "r"(a[2]), "r"(a[3]), "r"(b[0]), "r"(b[1]));
}

// ---------------------------------------------------------------------------
// GEMM: C[M,NSTR] = (Ahi+Alo)@(Bhi+Blo)^T, 2-stage cp.async, 1 sync/k-iter.
// HOUT: store output as fp16 (for hs buffers); else fp32.
// ---------------------------------------------------------------------------
template<int NSTR, bool BIAS, bool HOUT>
__global__ __launch_bounds__(256)
void gemm_kernel(const bf16* __restrict__ Ahi, const bf16* __restrict__ Alo,
                 const bf16* __restrict__ Bhi, const bf16* __restrict__ Blo,
                 const float* __restrict__ bias, void* __restrict__ Cv, int M) {
    extern __shared__ __align__(128) char smg[];
    const uint32_t sb = smem_u32(smg);
    const int tid = threadIdx.x, lane = tid & 31, wid = tid >> 5;
    const int wm = wid >> 2, wn = wid & 3;
    const int mt = (M + 127) / 128;
    const int bm = (blockIdx.x % mt) * 128, bn = (blockIdx.x / mt) * 128;

    const char* src[4] = {
        (const char*)(Ahi + (size_t)bm * 256), (const char*)(Alo + (size_t)bm * 256),
        (const char*)(Bhi + (size_t)bn * 256), (const char*)(Blo + (size_t)bn * 256)};

    uint32_t aBH[4], aBL[4], bBH[2], bBL[2];
    {
        int ar = wm * 64 + (lane & 15), ac = (lane >> 4) * 8;
        #pragma unroll
        for (int i = 0; i < 4; i++) {
            aBH[i] = sb + (uint32_t)(ar + i * 16) * 80 + ac * 2;
            aBL[i] = aBH[i] + 10240;
        }
        int br = wn * 32 + ((lane >> 4) << 3) + (lane & 7);
        int bc = ((lane >> 3) & 1) * 8;
        #pragma unroll
        for (int p = 0; p < 2; p++) {
            bBH[p] = sb + 20480 + (uint32_t)(br + p * 16) * 80 + bc * 2;
            bBL[p] = bBH[p] + 10240;
        }
    }

    float acc[4][4][4];
    #pragma unroll
    for (int i = 0; i < 4; i++)
        #pragma unroll
        for (int j = 0; j < 4; j++)
            #pragma unroll
            for (int q = 0; q < 4; q++) acc[i][j][q] = 0.f;

    auto load_stage = [&](int kc, int buf) {
        #pragma unroll
        for (int arr = 0; arr < 4; arr++) {
            const char* s = src[arr] + kc * 64;
            uint32_t d = sb + buf * 40960 + arr * 10240;
            #pragma unroll
            for (int t2 = 0; t2 < 2; t2++) {
                int cid = t2 * 256 + tid, row = cid >> 2, c = cid & 3;
                cp16(d + row * 80 + c * 16, s + (size_t)row * 512 + c * 16);
            }
        }
        asm volatile("cp.async.commit_group;");
    };

    load_stage(0, 0);
    for (int kc = 0; kc < 8; kc++) {
        int buf = kc & 1;
        asm volatile("cp.async.wait_group 0;");
        __syncthreads();
        if (kc < 7) load_stage(kc + 1, buf ^ 1);
        uint32_t bo = (uint32_t)buf * 40960;
        #pragma unroll
        for (int ks = 0; ks < 2; ks++) {
            uint32_t ah[4][4], al[4][4], bh[4][2], bl[4][2];
            #pragma unroll
            for (int i = 0; i < 4; i++) {
                ldsm4(ah[i][0], ah[i][1], ah[i][2], ah[i][3], aBH[i] + bo + ks * 32);
                ldsm4(al[i][0], al[i][1], al[i][2], al[i][3], aBL[i] + bo + ks * 32);
            }
            #pragma unroll
            for (int p = 0; p < 2; p++) {
                uint32_t r0, r1, r2, r3;
                ldsm4(r0, r1, r2, r3, bBH[p] + bo + ks * 32);
                bh[p * 2][0] = r0; bh[p * 2][1] = r1;
                bh[p * 2 + 1][0] = r2; bh[p * 2 + 1][1] = r3;
                ldsm4(r0, r1, r2, r3, bBL[p] + bo + ks * 32);
                bl[p * 2][0] = r0; bl[p * 2][1] = r1;
                bl[p * 2 + 1][0] = r2; bl[p * 2 + 1][1] = r3;
            }
            #pragma unroll
            for (int i = 0; i < 4; i++)
                #pragma unroll
                for (int j = 0; j < 4; j++) {
                    mma_bf16(acc[i][j], ah[i], bh[j]);
                    mma_bf16(acc[i][j], ah[i], bl[j]);
                    mma_bf16(acc[i][j], al[i], bh[j]);
                }
        }
    }

    #pragma unroll
    for (int i = 0; i < 4; i++) {
        int r0 = bm + wm * 64 + i * 16 + (lane >> 2);
        #pragma unroll
        for (int j = 0; j < 4; j++) {
            int cc = bn + wn * 32 + j * 8 + 2 * (lane & 3);
            float b0 = 0.f, b1 = 0.f;
            if (BIAS) { b0 = __ldg(&bias[cc]); b1 = __ldg(&bias[cc + 1]); }
            if (HOUT) {
                __half* C = (__half*)Cv;
                if (r0 < M)
                    *(__half2*)&C[(size_t)r0 * NSTR + cc] =
                        __floats2half2_rn(acc[i][j][0] + b0, acc[i][j][1] + b1);
                if (r0 + 8 < M)
                    *(__half2*)&C[(size_t)(r0 + 8) * NSTR + cc] =
                        __floats2half2_rn(acc[i][j][2] + b0, acc[i][j][3] + b1);
            } else {
                float* C = (float*)Cv;
                if (r0 < M)
                    *(float2*)&C[(size_t)r0 * NSTR + cc] =
                        make_float2(acc[i][j][0] + b0, acc[i][j][1] + b1);
                if (r0 + 8 < M)
                    *(float2*)&C[(size_t)(r0 + 8) * NSTR + cc] =
                        make_float2(acc[i][j][2] + b0, acc[i][j][3] + b1);
            }
        }
    }
}

// ---------------------------------------------------------------------------
// Aggregation (warp/node): softmax + gather(fp16 hs) + bias + relu,
// bf16 hi/lo out. AUX=1: auxout[n,h] = out_row . auxT[h]
// ---------------------------------------------------------------------------
__device__ __forceinline__ void acc_half8(float* acc, float w, uint4 d) {
    __half2* hh = (__half2*)&d;
    #pragma unroll
    for (int q = 0; q < 4; q++) {
        float2 f = __half22float2(hh[q]);
        acc[q * 2]     = fmaf(w, f.x, acc[q * 2]);
        acc[q * 2 + 1] = fmaf(w, f.y, acc[q * 2 + 1]);
    }
}

template<int AUX>
__global__ __launch_bounds__(256)
void agg_kernel(const __half* __restrict__ hs, const float* __restrict__ es,
                const float* __restrict__ ed, const int* __restrict__ rowptr,
                const int* __restrict__ csrc, const float* __restrict__ bias,
                bf16* __restrict__ outhi, bf16* __restrict__ outlo,
                const float* __restrict__ auxT, float* __restrict__ auxout,
                int Nd) {
    __shared__ float saux[1024];
    if (AUX) {
        for (int i = threadIdx.x; i < 1024; i += 256) saux[i] = auxT[i];
        __syncthreads();
    }
    int warp = blockIdx.x * 8 + (threadIdx.x >> 5);
    int lane = threadIdx.x & 31;
    if (warp >= Nd) return;
    int h = lane >> 3;
    float edh = ed[warp * 4 + h];
    int beg = rowptr[warp], end = rowptr[warp + 1];
    float denom = 0.f;
    float acc[8] = {0.f, 0.f, 0.f, 0.f, 0.f, 0.f, 0.f, 0.f};
    int e = beg;
    for (; e + 2 <= end; e += 2) {
        int s0 = csrc[e], s1 = csrc[e + 1];
        float a0 = es[s0 * 4 + h] + edh;
        float a1 = es[s1 * 4 + h] + edh;
        a0 = (a0 > 0.f) ? a0 : a0 * NEG_SLOPE;
        a1 = (a1 > 0.f) ? a1 : a1 * NEG_SLOPE;
        float w0 = __expf(a0), w1 = __expf(a1);
        denom += w0 + w1;
        uint4 d0 = *(const uint4*)&hs[(size_t)s0 * 256 + lane * 8];
        uint4 d1 = *(const uint4*)&hs[(size_t)s1 * 256 + lane * 8];
        acc_half8(acc, w0, d0);
        acc_half8(acc, w1, d1);
    }
    if (e < end) {
        int s = csrc[e];
        float a = es[s * 4 + h] + edh;
        a = (a > 0.f) ? a : a * NEG_SLOPE;
        float w = __expf(a);
        denom += w;
        uint4 d = *(const uint4*)&hs[(size_t)s * 256 + lane * 8];
        acc_half8(acc, w, d);
    }
    float inv = 1.f / (denom + EPS_F);
    const float4* bp = (const float4*)&bias[lane * 8];
    float4 b0 = bp[0], b1 = bp[1];
    float o[8];
    o[0] = fmaxf(acc[0] * inv + b0.x, 0.f);
    o[1] = fmaxf(acc[1] * inv + b0.y, 0.f);
    o[2] = fmaxf(acc[2] * inv + b0.z, 0.f);
    o[3] = fmaxf(acc[3] * inv + b0.w, 0.f);
    o[4] = fmaxf(acc[4] * inv + b1.x, 0.f);
    o[5] = fmaxf(acc[5] * inv + b1.y, 0.f);
    o[6] = fmaxf(acc[6] * inv + b1.z, 0.f);
    o[7] = fmaxf(acc[7] * inv + b1.w, 0.f);

    uint32_t hw[4], lw[4];
    #pragma unroll
    for (int q = 0; q < 4; q++) {
        bf16 ha = __float2bfloat16(o[q * 2]), hb = __float2bfloat16(o[q * 2 + 1]);
        __nv_bfloat162 hp(ha, hb);
        __nv_bfloat162 lp(__float2bfloat16(o[q * 2] - __bfloat162float(ha)),
                          __float2bfloat16(o[q * 2 + 1] - __bfloat162float(hb)));
        hw[q] = *(uint32_t*)&hp;
        lw[q] = *(uint32_t*)&lp;
    }
    *(uint4*)&outhi[(size_t)warp * 256 + lane * 8] =
        make_uint4(hw[0], hw[1], hw[2], hw[3]);
    *(uint4*)&outlo[(size_t)warp * 256 + lane * 8] =
        make_uint4(lw[0], lw[1], lw[2], lw[3]);

    if (AUX) {
        const float4* sT4 = (const float4*)saux;
        float ph[4];
        #pragma unroll
        for (int hh = 0; hh < 4; hh++) {
            float4 c0 = sT4[hh * 64 + lane * 2], c1 = sT4[hh * 64 + lane * 2 + 1];
            float p = o[0] * c0.x + o[1] * c0.y + o[2] * c0.z + o[3] * c0.w
                    + o[4] * c1.x + o[5] * c1.y + o[6] * c1.z + o[7] * c1.w;
            p += __shfl_xor_sync(0xffffffff, p, 16);
            p += __shfl_xor_sync(0xffffffff, p, 8);
            p += __shfl_xor_sync(0xffffffff, p, 4);
            p += __shfl_xor_sync(0xffffffff, p, 2);
            p += __shfl_xor_sync(0xffffffff, p, 1);
            ph[hh] = p;
        }
        if (lane == 0)
            ((float4*)auxout)[warp] = make_float4(ph[0], ph[1], ph[2], ph[3]);
    }
}

// ---------------------------------------------------------------------------
// prep_smat_all / wconv_all / splitsmall  (R11-proven kernels)
// ---------------------------------------------------------------------------
__global__ void prep_smat_all(const float* __restrict__ Ws,
                              const float* __restrict__ Wd,
                              const float* __restrict__ as_,
                              const float* __restrict__ ad_,
                              float* __restrict__ cmbT_u,
                              float* __restrict__ cmbT_v,
                              float* __restrict__ wsatt2T,
                              float* __restrict__ vd2T) {
    int k = threadIdx.x, b = blockIdx.x;
    auto dot = [&](const float* W, const float* a, int h) {
        float s = 0.f;
        #pragma unroll 8
        for (int c = 0; c < 64; c++)
            s = fmaf(W[(size_t)k * 256 + h * 64 + c], a[h * 64 + c], s);
        return s;
    };
    if (b == 0) {
        for (int h = 0; h < 4; h++) cmbT_u[h * 256 + k] = dot(Ws, as_, h);
        for (int h = 0; h < 4; h++)
            cmbT_u[(4 + h) * 256 + k] = dot(Wd + 65536, ad_ + 256, h);
    } else if (b == 1) {
        for (int h = 0; h < 4; h++)
            cmbT_v[h * 256 + k] = dot(Ws + 65536, as_ + 256, h);
        for (int h = 0; h < 4; h++) cmbT_v[(4 + h) * 256 + k] = dot(Wd, ad_, h);
    } else if (b == 2) {
        for (int h = 0; h < 4; h++)
            wsatt2T[h * 256 + k] = dot(Ws + 3 * 65536, as_ + 3 * 256, h);
    } else {
        for (int h = 0; h < 4; h++)
            vd2T[h * 256 + k] = dot(Wd + 3 * 65536, ad_ + 3 * 256, h);
    }
}

__global__ void wconv_all(const float* __restrict__ W_src,
                          const float* __restrict__ lin_w,
                          bf16* __restrict__ wt_hi, bf16* __restrict__ wt_lo,
                          bf16* __restrict__ lt_hi, bf16* __restrict__ lt_lo) {
    int b = blockIdx.x, k = threadIdx.x;
    if (b < 768) {
        int sl = b >> 8, n = b & 255;
        const float* W = W_src + (size_t)(sl == 2 ? 3 : sl) * 65536;
        float f = W[(size_t)k * 256 + n];
        bf16 h = __float2bfloat16(f);
        wt_hi[((size_t)sl * 256 + n) * 256 + k] = h;
        wt_lo[((size_t)sl * 256 + n) * 256 + k] =
            __float2bfloat16(f - __bfloat162float(h));
    } else {
        int n = b - 768;
        float f = lin_w[(size_t)k * 128 + n];
        bf16 h = __float2bfloat16(f);
        lt_hi[(size_t)n * 256 + k] = h;
        lt_lo[(size_t)n * 256 + k] = __float2bfloat16(f - __bfloat162float(h));
    }
}

__global__ __launch_bounds__(256)
void splitsmall_kernel(const float* __restrict__ x, const float* __restrict__ cmbT,
                       bf16* __restrict__ hi, bf16* __restrict__ lo,
                       float* __restrict__ es, float* __restrict__ ed, int N) {
    __shared__ float sT[2048];
    for (int i = threadIdx.x; i < 2048; i += 256) sT[i] = cmbT[i];
    __syncthreads();
    int warp = (blockIdx.x * 256 + threadIdx.x) >> 5;
    int lane = threadIdx.x & 31;
    if (warp >= N) return;
    const float4* row = (const float4*)&x[(size_t)warp * 256 + lane * 8];
    float4 a0 = row[0], a1 = row[1];
    float v[8] = {a0.x, a0.y, a0.z, a0.w, a1.x, a1.y, a1.z, a1.w};

    uint32_t hw[4], lw[4];
    #pragma unroll
    for (int q = 0; q < 4; q++) {
        bf16 ha = __float2bfloat16(v[q * 2]), hb = __float2bfloat16(v[q * 2 + 1]);
        __nv_bfloat162 hp(ha, hb);
        __nv_bfloat162 lp(__float2bfloat16(v[q * 2] - __bfloat162float(ha)),
                          __float2bfloat16(v[q * 2 + 1] - __bfloat162float(hb)));
        hw[q] = *(uint32_t*)&hp;
        lw[q] = *(uint32_t*)&lp;
    }
    *(uint4*)&hi[(size_t)warp * 256 + lane * 8] = make_uint4(hw[0], hw[1], hw[2], hw[3]);
    *(uint4*)&lo[(size_t)warp * 256 + lane * 8] = make_uint4(lw[0], lw[1], lw[2], lw[3]);

    const float4* sT4 = (const float4*)sT;
    float p[8];
    #pragma unroll
    for (int h = 0; h < 8; h++) {
        float4 c0 = sT4[h * 64 + lane * 2], c1 = sT4[h * 64 + lane * 2 + 1];
        p[h] = a0.x * c0.x + a0.y * c0.y + a0.z * c0.z + a0.w * c0.w
             + a1.x * c1.x + a1.y * c1.y + a1.z * c1.z + a1.w * c1.w;
    }
    #pragma unroll
    for (int h = 0; h < 8; h++) {
        p[h] += __shfl_xor_sync(0xffffffff, p[h], 16);
        p[h] += __shfl_xor_sync(0xffffffff, p[h], 8);
        p[h] += __shfl_xor_sync(0xffffffff, p[h], 4);
        p[h] += __shfl_xor_sync(0xffffffff, p[h], 2);
        p[h] += __shfl_xor_sync(0xffffffff, p[h], 1);
    }
    if (lane == 0) {
        ((float4*)es)[warp] = make_float4(p[0], p[1], p[2], p[3]);
        ((float4*)ed)[warp] = make_float4(p[4], p[5], p[6], p[7]);
    }
}

// ---------------------------------------------------------------------------
// CSR build — both relations concatenated (R11-proven kernels)
// ---------------------------------------------------------------------------
__global__ void zero_kernel(int* p, int n) {
    int i = blockIdx.x * blockDim.x + threadIdx.x;
    if (i < n) p[i] = 0;
}

__global__ void count2_kernel(const int* __restrict__ euv,
                              const int* __restrict__ evu,
                              int* __restrict__ cnt) {
    int e = blockIdx.x * blockDim.x + threadIdx.x;
    if (e < NE) atomicAdd(&cnt[euv[NE + e]], 1);
    else if (e < 2 * NE) atomicAdd(&cnt[50000 + evu[NE + (e - NE)]], 1);
}

__global__ __launch_bounds__(1024)
void scan1_kernel(const int* __restrict__ in, int* __restrict__ out,
                  int* __restrict__ bsums, int n) {
    __shared__ int sh[1024];
    int i = blockIdx.x * 1024 + threadIdx.x;
    int v = (i < n) ? in[i] : 0;
    sh[threadIdx.x] = v;
    __syncthreads();
    for (int off = 1; off < 1024; off <<= 1) {
        int t = (threadIdx.x >= off) ? sh[threadIdx.x - off] : 0;
        __syncthreads();
        sh[threadIdx.x] += t;
        __syncthreads();
    }
    if (i < n) out[i] = sh[threadIdx.x] - v;
    if (threadIdx.x == 1023) bsums[blockIdx.x] = sh[1023];
}

__global__ void scan2p_kernel(int* bsums, int nb) {
    __shared__ int sh[128];
    int t = threadIdx.x;
    int v = (t < nb) ? bsums[t] : 0;
    sh[t] = v;
    __syncthreads();
    for (int off = 1; off < 128; off <<= 1) {
        int x = (t >= off) ? sh[t - off] : 0;
        __syncthreads();
        sh[t] += x;
        __syncthreads();
    }
    if (t < nb) bsums[t] = sh[t] - v;   // exclusive
}

__global__ void scan3_kernel(int* out, const int* __restrict__ bsums, int n,
                             int total) {
    int i = blockIdx.x * blockDim.x + threadIdx.x;
    if (i < n) out[i] += bsums[i >> 10];
    if (i == 0) out[n] = total;
}

__global__ void fill2_kernel(const int* __restrict__ euv,
                             const int* __restrict__ evu,
                             const int* __restrict__ rowptr,
                             int* __restrict__ cursor, int* __restrict__ csrc) {
    int e = blockIdx.x * blockDim.x + threadIdx.x;
    if (e >= 2 * NE) return;
    int s, d;
    if (e < NE) { s = euv[e]; d = euv[NE + e]; }
    else { int e2 = e - NE; s = evu[e2]; d = 50000 + evu[NE + e2]; }
    int pos = atomicAdd(&cursor[d], 1);
    csrc[rowptr[d] + pos] = s;
}

// ---------------------------------------------------------------------------
// Host — single stream, plain launches only
// ---------------------------------------------------------------------------
static inline void* sym(const void* s) {
    void* p = nullptr;
    cudaGetSymbolAddress(&p, s);
    return p;
}

extern "C" void kernel_launch(void* const* d_in, const int* in_sizes, int n_in,
                              void* d_out, int out_size) {
    const float* x_u   = (const float*)d_in[0];
    const float* x_v   = (const float*)d_in[1];
    const float* W_src = (const float*)d_in[2];
    const float* W_dst = (const float*)d_in[3];
    const float* att_s = (const float*)d_in[4];
    const float* att_d = (const float*)d_in[5];
    const float* bias  = (const float*)d_in[6];
    const float* lin_w = (const float*)d_in[7];
    const float* lin_b = (const float*)d_in[8];
    const int* ei_uv   = (const int*)d_in[9];
    const int* ei_vu   = (const int*)d_in[10];
    float* out = (float*)d_out;

    __half *hs0 = (__half*)sym(g_hs0), *hs1 = (__half*)sym(g_hs1);
    bf16 *xu_hi = (bf16*)sym(g_xu_hi), *xu_lo = (bf16*)sym(g_xu_lo);
    bf16 *xv_hi = (bf16*)sym(g_xv_hi), *xv_lo = (bf16*)sym(g_xv_lo);
    bf16 *nv0_hi = (bf16*)sym(g_nv0_hi), *nv0_lo = (bf16*)sym(g_nv0_lo);
    bf16 *nu0_hi = (bf16*)sym(g_nu0_hi), *nu0_lo = (bf16*)sym(g_nu0_lo);
    bf16 *nu1_hi = (bf16*)sym(g_nu1_hi), *nu1_lo = (bf16*)sym(g_nu1_lo);
    float *es0 = (float*)sym(g_es0), *es1 = (float*)sym(g_es1), *es2 = (float*)sym(g_es2);
    float *ed0 = (float*)sym(g_ed0), *ed1 = (float*)sym(g_ed1), *ed2 = (float*)sym(g_ed2);
    float *cmbT_u = (float*)sym(g_cmbT_u), *cmbT_v = (float*)sym(g_cmbT_v);
    float *wsatt2T = (float*)sym(g_wsatt2T), *vd2T = (float*)sym(g_vd2T);
    bf16 *wt_hi = (bf16*)sym(g_wt_hi), *wt_lo = (bf16*)sym(g_wt_lo);
    bf16 *lt_hi = (bf16*)sym(g_lt_hi), *lt_lo = (bf16*)sym(g_lt_lo);
    int *rowptr = (int*)sym(g_rowptr), *csrc = (int*)sym(g_csrc);
    int *cnt = (int*)sym(g_cnt), *bsums = (int*)sym(g_bsums);

    cudaFuncSetAttribute(gemm_kernel<256, false, true>,
                         cudaFuncAttributeMaxDynamicSharedMemorySize, GSMEM);
    cudaFuncSetAttribute(gemm_kernel<128, true, false>,
                         cudaFuncAttributeMaxDynamicSharedMemorySize, GSMEM);

    const size_t WSZ = 256 * 256, BSZ = 256;
    const int NB = (NALL + 1023) / 1024;   // 98

    // L0: tiny attention matrices
    prep_smat_all<<<4, 256>>>(W_src, W_dst, att_s, att_d,
                              cmbT_u, cmbT_v, wsatt2T, vd2T);
    // L1: weight convert
    wconv_all<<<896, 256>>>(W_src, lin_w, wt_hi, wt_lo, lt_hi, lt_lo);
    // L2: split + es0/ed1 for x_u
    splitsmall_kernel<<<6250, 256>>>(x_u, cmbT_u, xu_hi, xu_lo, es0, ed1, NU);
    // L3: gemm0 -> hs0 (fp16)   (ncu capture index)
    gemm_kernel<256, false, true><<<782, 256, GSMEM>>>(
        xu_hi, xu_lo, wt_hi + 0 * WSZ, wt_lo + 0 * WSZ, nullptr, hs0, NU);
    // L4: split + es1/ed0 for x_v
    splitsmall_kernel<<<6250, 256>>>(x_v, cmbT_v, xv_hi, xv_lo, es1, ed0, NV);
    // L5-L11: CSR (both relations concatenated)
    zero_kernel<<<(NALL + 255) / 256, 256>>>(cnt, NALL);
    count2_kernel<<<(2 * NE + 255) / 256, 256>>>(ei_uv, ei_vu, cnt);
    scan1_kernel<<<NB, 1024>>>(cnt, rowptr, bsums, NALL);
    scan2p_kernel<<<1, 128>>>(bsums, NB);
    scan3_kernel<<<(NALL + 255) / 256, 256>>>(rowptr, bsums, NALL, 2 * NE);
    zero_kernel<<<(NALL + 255) / 256, 256>>>(cnt, NALL);
    fill2_kernel<<<(2 * NE + 255) / 256, 256>>>(ei_uv, ei_vu, rowptr, cnt, csrc);

    // L12: agg0 (hs0 -> nv0, +es2)
    agg_kernel<1><<<6250, 256>>>(hs0, es0, ed0, rowptr, csrc, bias + 0 * BSZ,
                                 nv0_hi, nv0_lo, wsatt2T, es2, NV);
    // L13: gemm1 (xv -> hs1, fp16)
    gemm_kernel<256, false, true><<<782, 256, GSMEM>>>(
        xv_hi, xv_lo, wt_hi + 1 * WSZ, wt_lo + 1 * WSZ, nullptr, hs1, NV);
    // L14: agg1 (hs1 -> nu0, +ed2)
    agg_kernel<1><<<6250, 256>>>(hs1, es1, ed1, rowptr + 50000, csrc,
                                 bias + 1 * BSZ, nu0_hi, nu0_lo, vd2T, ed2, NU);
    // L15: gemm2 (nv0 -> hs0, fp16)
    gemm_kernel<256, false, true><<<782, 256, GSMEM>>>(
        nv0_hi, nv0_lo, wt_hi + 2 * WSZ, wt_lo + 2 * WSZ, nullptr, hs0, NV);
    // L16: agg2 (hs0 -> nu1)
    agg_kernel<0><<<6250, 256>>>(hs0, es2, ed2, rowptr + 50000, csrc,
                                 bias + 3 * BSZ, nu1_hi, nu1_lo,
                                 nullptr, nullptr, NU);
    // L17: final linear (fp32 out)
    gemm_kernel<128, true, false><<<391, 256, GSMEM>>>(
        nu1_hi, nu1_lo, lt_hi, lt_lo, lin_b, out, NU);
}

// round 14
// speedup vs baseline: 1.4900x; 1.1315x over previous
#include <cuda_runtime.h>
#include <cuda_bf16.h>
#include <cuda_fp16.h>
#include <cstdint>

typedef __nv_bfloat16 bf16;

static const int NU = 50000;
static const int NV = 50000;
static const int NE = 500000;
static const int NALL = 100000;          // concatenated dst-node space
#define NEG_SLOPE 0.2f
#define EPS_F 1e-16f
#define GSMEM 81920
#define GSMEM16 40960

// ---------------------------------------------------------------------------
// Static device scratch
// ---------------------------------------------------------------------------
__device__ __align__(128) __half g_hs0[50048 * 256];
__device__ __align__(128) __half g_hs1[50048 * 256];
__device__ __align__(128) bf16 g_xu_hi[50048 * 256], g_xu_lo[50048 * 256];
__device__ __align__(128) bf16 g_xv_hi[50048 * 256], g_xv_lo[50048 * 256];
__device__ __align__(128) __half g_nv0h[50048 * 256];
__device__ __align__(128) __half g_nu1h[50048 * 256];
__device__ __align__(128) float g_es0[50048 * 4], g_es1[50048 * 4], g_es2[50048 * 4];
__device__ __align__(128) float g_ed0[50048 * 4], g_ed1[50048 * 4], g_ed2[50048 * 4];
__device__ __align__(128) float g_cmbT_u[8 * 256], g_cmbT_v[8 * 256];
__device__ __align__(128) float g_wsatt2T[4 * 256], g_vd2T[4 * 256];
__device__ __align__(128) bf16 g_wt_hi[2 * 256 * 256], g_wt_lo[2 * 256 * 256];
__device__ __align__(128) __half g_wt2h[256 * 256];
__device__ __align__(128) __half g_lth[128 * 256];
__device__ __align__(128) int g_rowptr[100001];
__device__ __align__(128) int g_csrc[1000000];
__device__ __align__(128) int g_cnt[100001], g_bsums[128];

// ---------------------------------------------------------------------------
// helpers
// ---------------------------------------------------------------------------
__device__ __forceinline__ uint32_t smem_u32(const void* p) {
    uint32_t a;
    asm("{ .reg .u64 t; cvta.to.shared.u64 t, %1; cvt.u32.u64 %0, t; }"
        : "=r"(a) : "l"(p));
    return a;
}

__device__ __forceinline__ void cp16(uint32_t dst, const void* src) {
    asm volatile("cp.async.cg.shared.global [%0], [%1], 16;"
                 :: "r"(dst), "l"(src));
}

__device__ __forceinline__ void ldsm4(uint32_t& r0, uint32_t& r1, uint32_t& r2,
                                      uint32_t& r3, uint32_t addr) {
    asm volatile("ldmatrix.sync.aligned.m8n8.x4.shared.b16 {%0,%1,%2,%3}, [%4];"
                 : "=r"(r0), "=r"(r1), "=r"(r2), "=r"(r3) : "r"(addr));
}

__device__ __forceinline__ void mma_bf16(float* c, const uint32_t* a,
                                         const uint32_t* b) {
    asm volatile(
        "mma.sync.aligned.m16n8k16.row.col.f32.bf16.bf16.f32 "
        "{%0,%1,%2,%3}, {%4,%5,%6,%7}, {%8,%9}, {%0,%1,%2,%3};"
        : "+f"(c[0]), "+f"(c[1]), "+f"(c[2]), "+f"(c[3])
        : "r"(a[0]), "r"(a[1]), "r"(a[2]), "r"(a[3]), "r"(b[0]), "r"(b[1]));
}

__device__ __forceinline__ void mma_fp16(float* c, const uint32_t* a,
                                         const uint32_t* b) {
    asm volatile(
        "mma.sync.aligned.m16n8k16.row.col.f32.f16.f16.f32 "
        "{%0,%1,%2,%3}, {%4,%5,%6,%7}, {%8,%9}, {%0,%1,%2,%3};"
        : "+f"(c[0]), "+f"(c[1]), "+f"(c[2]), "+f"(c[3])
        : "r"(a[0]), "r"(a[1]), "r"(a[2]), "r"(a[3]), "r"(b[0]), "r"(b[1]));
}

// ---------------------------------------------------------------------------
// GEMM (bf16 2-term split): C = (Ahi+Alo)@(Bhi+Blo)^T.  HOUT: fp16 out.
// (R13-proven kernel, unchanged)
// ---------------------------------------------------------------------------
template<int NSTR, bool BIAS, bool HOUT>
__global__ __launch_bounds__(256)
void gemm_kernel(const bf16* __restrict__ Ahi, const bf16* __restrict__ Alo,
                 const bf16* __restrict__ Bhi, const bf16* __restrict__ Blo,
                 const float* __restrict__ bias, void* __restrict__ Cv, int M) {
    extern __shared__ __align__(128) char smg[];
    const uint32_t sb = smem_u32(smg);
    const int tid = threadIdx.x, lane = tid & 31, wid = tid >> 5;
    const int wm = wid >> 2, wn = wid & 3;
    const int mt = (M + 127) / 128;
    const int bm = (blockIdx.x % mt) * 128, bn = (blockIdx.x / mt) * 128;

    const char* src[4] = {
        (const char*)(Ahi + (size_t)bm * 256), (const char*)(Alo + (size_t)bm * 256),
        (const char*)(Bhi + (size_t)bn * 256), (const char*)(Blo + (size_t)bn * 256)};

    uint32_t aBH[4], aBL[4], bBH[2], bBL[2];
    {
        int ar = wm * 64 + (lane & 15), ac = (lane >> 4) * 8;
        #pragma unroll
        for (int i = 0; i < 4; i++) {
            aBH[i] = sb + (uint32_t)(ar + i * 16) * 80 + ac * 2;
            aBL[i] = aBH[i] + 10240;
        }
        int br = wn * 32 + ((lane >> 4) << 3) + (lane & 7);
        int bc = ((lane >> 3) & 1) * 8;
        #pragma unroll
        for (int p = 0; p < 2; p++) {
            bBH[p] = sb + 20480 + (uint32_t)(br + p * 16) * 80 + bc * 2;
            bBL[p] = bBH[p] + 10240;
        }
    }

    float acc[4][4][4];
    #pragma unroll
    for (int i = 0; i < 4; i++)
        #pragma unroll
        for (int j = 0; j < 4; j++)
            #pragma unroll
            for (int q = 0; q < 4; q++) acc[i][j][q] = 0.f;

    auto load_stage = [&](int kc, int buf) {
        #pragma unroll
        for (int arr = 0; arr < 4; arr++) {
            const char* s = src[arr] + kc * 64;
            uint32_t d = sb + buf * 40960 + arr * 10240;
            #pragma unroll
            for (int t2 = 0; t2 < 2; t2++) {
                int cid = t2 * 256 + tid, row = cid >> 2, c = cid & 3;
                cp16(d + row * 80 + c * 16, s + (size_t)row * 512 + c * 16);
            }
        }
        asm volatile("cp.async.commit_group;");
    };

    load_stage(0, 0);
    for (int kc = 0; kc < 8; kc++) {
        int buf = kc & 1;
        asm volatile("cp.async.wait_group 0;");
        __syncthreads();
        if (kc < 7) load_stage(kc + 1, buf ^ 1);
        uint32_t bo = (uint32_t)buf * 40960;
        #pragma unroll
        for (int ks = 0; ks < 2; ks++) {
            uint32_t ah[4][4], al[4][4], bh[4][2], bl[4][2];
            #pragma unroll
            for (int i = 0; i < 4; i++) {
                ldsm4(ah[i][0], ah[i][1], ah[i][2], ah[i][3], aBH[i] + bo + ks * 32);
                ldsm4(al[i][0], al[i][1], al[i][2], al[i][3], aBL[i] + bo + ks * 32);
            }
            #pragma unroll
            for (int p = 0; p < 2; p++) {
                uint32_t r0, r1, r2, r3;
                ldsm4(r0, r1, r2, r3, bBH[p] + bo + ks * 32);
                bh[p * 2][0] = r0; bh[p * 2][1] = r1;
                bh[p * 2 + 1][0] = r2; bh[p * 2 + 1][1] = r3;
                ldsm4(r0, r1, r2, r3, bBL[p] + bo + ks * 32);
                bl[p * 2][0] = r0; bl[p * 2][1] = r1;
                bl[p * 2 + 1][0] = r2; bl[p * 2 + 1][1] = r3;
            }
            #pragma unroll
            for (int i = 0; i < 4; i++)
                #pragma unroll
                for (int j = 0; j < 4; j++) {
                    mma_bf16(acc[i][j], ah[i], bh[j]);
                    mma_bf16(acc[i][j], ah[i], bl[j]);
                    mma_bf16(acc[i][j], al[i], bh[j]);
                }
        }
    }

    #pragma unroll
    for (int i = 0; i < 4; i++) {
        int r0 = bm + wm * 64 + i * 16 + (lane >> 2);
        #pragma unroll
        for (int j = 0; j < 4; j++) {
            int cc = bn + wn * 32 + j * 8 + 2 * (lane & 3);
            float b0 = 0.f, b1 = 0.f;
            if (BIAS) { b0 = __ldg(&bias[cc]); b1 = __ldg(&bias[cc + 1]); }
            if (HOUT) {
                __half* C = (__half*)Cv;
                if (r0 < M)
                    *(__half2*)&C[(size_t)r0 * NSTR + cc] =
                        __floats2half2_rn(acc[i][j][0] + b0, acc[i][j][1] + b1);
                if (r0 + 8 < M)
                    *(__half2*)&C[(size_t)(r0 + 8) * NSTR + cc] =
                        __floats2half2_rn(acc[i][j][2] + b0, acc[i][j][3] + b1);
            } else {
                float* C = (float*)Cv;
                if (r0 < M)
                    *(float2*)&C[(size_t)r0 * NSTR + cc] =
                        make_float2(acc[i][j][0] + b0, acc[i][j][1] + b1);
                if (r0 + 8 < M)
                    *(float2*)&C[(size_t)(r0 + 8) * NSTR + cc] =
                        make_float2(acc[i][j][2] + b0, acc[i][j][3] + b1);
            }
        }
    }
}

// ---------------------------------------------------------------------------
// GEMM16 (single-term fp16): C = A@B^T, A/B fp16.  16 MMAs/k-step.
// Same tiling/pipeline as gemm_kernel, SMEM halved (2 arrays).
// ---------------------------------------------------------------------------
template<int NSTR, bool BIAS, bool HOUT>
__global__ __launch_bounds__(256)
void gemm16_kernel(const __half* __restrict__ A, const __half* __restrict__ B,
                   const float* __restrict__ bias, void* __restrict__ Cv, int M) {
    extern __shared__ __align__(128) char smg[];
    const uint32_t sb = smem_u32(smg);
    const int tid = threadIdx.x, lane = tid & 31, wid = tid >> 5;
    const int wm = wid >> 2, wn = wid & 3;
    const int mt = (M + 127) / 128;
    const int bm = (blockIdx.x % mt) * 128, bn = (blockIdx.x / mt) * 128;

    const char* src[2] = {(const char*)(A + (size_t)bm * 256),
                          (const char*)(B + (size_t)bn * 256)};

    uint32_t aB[4], bB[2];
    {
        int ar = wm * 64 + (lane & 15), ac = (lane >> 4) * 8;
        #pragma unroll
        for (int i = 0; i < 4; i++)
            aB[i] = sb + (uint32_t)(ar + i * 16) * 80 + ac * 2;
        int br = wn * 32 + ((lane >> 4) << 3) + (lane & 7);
        int bc = ((lane >> 3) & 1) * 8;
        #pragma unroll
        for (int p = 0; p < 2; p++)
            bB[p] = sb + 10240 + (uint32_t)(br + p * 16) * 80 + bc * 2;
    }

    float acc[4][4][4];
    #pragma unroll
    for (int i = 0; i < 4; i++)
        #pragma unroll
        for (int j = 0; j < 4; j++)
            #pragma unroll
            for (int q = 0; q < 4; q++) acc[i][j][q] = 0.f;

    auto load_stage = [&](int kc, int buf) {
        #pragma unroll
        for (int arr = 0; arr < 2; arr++) {
            const char* s = src[arr] + kc * 64;
            uint32_t d = sb + buf * 20480 + arr * 10240;
            #pragma unroll
            for (int t2 = 0; t2 < 2; t2++) {
                int cid = t2 * 256 + tid, row = cid >> 2, c = cid & 3;
                cp16(d + row * 80 + c * 16, s + (size_t)row * 512 + c * 16);
            }
        }
        asm volatile("cp.async.commit_group;");
    };

    load_stage(0, 0);
    for (int kc = 0; kc < 8; kc++) {
        int buf = kc & 1;
        asm volatile("cp.async.wait_group 0;");
        __syncthreads();
        if (kc < 7) load_stage(kc + 1, buf ^ 1);
        uint32_t bo = (uint32_t)buf * 20480;
        #pragma unroll
        for (int ks = 0; ks < 2; ks++) {
            uint32_t ah[4][4], bh[4][2];
            #pragma unroll
            for (int i = 0; i < 4; i++)
                ldsm4(ah[i][0], ah[i][1], ah[i][2], ah[i][3], aB[i] + bo + ks * 32);
            #pragma unroll
            for (int p = 0; p < 2; p++) {
                uint32_t r0, r1, r2, r3;
                ldsm4(r0, r1, r2, r3, bB[p] + bo + ks * 32);
                bh[p * 2][0] = r0; bh[p * 2][1] = r1;
                bh[p * 2 + 1][0] = r2; bh[p * 2 + 1][1] = r3;
            }
            #pragma unroll
            for (int i = 0; i < 4; i++)
                #pragma unroll
                for (int j = 0; j < 4; j++)
                    mma_fp16(acc[i][j], ah[i], bh[j]);
        }
    }

    #pragma unroll
    for (int i = 0; i < 4; i++) {
        int r0 = bm + wm * 64 + i * 16 + (lane >> 2);
        #pragma unroll
        for (int j = 0; j < 4; j++) {
            int cc = bn + wn * 32 + j * 8 + 2 * (lane & 3);
            float b0 = 0.f, b1 = 0.f;
            if (BIAS) { b0 = __ldg(&bias[cc]); b1 = __ldg(&bias[cc + 1]); }
            if (HOUT) {
                __half* C = (__half*)Cv;
                if (r0 < M)
                    *(__half2*)&C[(size_t)r0 * NSTR + cc] =
                        __floats2half2_rn(acc[i][j][0] + b0, acc[i][j][1] + b1);
                if (r0 + 8 < M)
                    *(__half2*)&C[(size_t)(r0 + 8) * NSTR + cc] =
                        __floats2half2_rn(acc[i][j][2] + b0, acc[i][j][3] + b1);
            } else {
                float* C = (float*)Cv;
                if (r0 < M)
                    *(float2*)&C[(size_t)r0 * NSTR + cc] =
                        make_float2(acc[i][j][0] + b0, acc[i][j][1] + b1);
                if (r0 + 8 < M)
                    *(float2*)&C[(size_t)(r0 + 8) * NSTR + cc] =
                        make_float2(acc[i][j][2] + b0, acc[i][j][3] + b1);
            }
        }
    }
}

// ---------------------------------------------------------------------------
// Aggregation: softmax + gather(fp16 hs) + bias + relu.
// OUT: 1 = store fp16 row, 0 = no output store (nu0 is dead).
// AUX=1: auxout[n,h] = out_row . auxT[h]  (fp32 registers, exact)
// ---------------------------------------------------------------------------
__device__ __forceinline__ void acc_half8(float* acc, float w, uint4 d) {
    __half2* hh = (__half2*)&d;
    #pragma unroll
    for (int q = 0; q < 4; q++) {
        float2 f = __half22float2(hh[q]);
        acc[q * 2]     = fmaf(w, f.x, acc[q * 2]);
        acc[q * 2 + 1] = fmaf(w, f.y, acc[q * 2 + 1]);
    }
}

template<int AUX, int OUT>
__global__ __launch_bounds__(256)
void agg_kernel(const __half* __restrict__ hs, const float* __restrict__ es,
                const float* __restrict__ ed, const int* __restrict__ rowptr,
                const int* __restrict__ csrc, const float* __restrict__ bias,
                __half* __restrict__ outh,
                const float* __restrict__ auxT, float* __restrict__ auxout,
                int Nd) {
    __shared__ float saux[1024];
    if (AUX) {
        for (int i = threadIdx.x; i < 1024; i += 256) saux[i] = auxT[i];
        __syncthreads();
    }
    int warp = blockIdx.x * 8 + (threadIdx.x >> 5);
    int lane = threadIdx.x & 31;
    if (warp >= Nd) return;
    int h = lane >> 3;
    float edh = ed[warp * 4 + h];
    int beg = rowptr[warp], end = rowptr[warp + 1];
    float denom = 0.f;
    float acc[8] = {0.f, 0.f, 0.f, 0.f, 0.f, 0.f, 0.f, 0.f};
    int e = beg;
    for (; e + 2 <= end; e += 2) {
        int s0 = csrc[e], s1 = csrc[e + 1];
        float a0 = es[s0 * 4 + h] + edh;
        float a1 = es[s1 * 4 + h] + edh;
        a0 = (a0 > 0.f) ? a0 : a0 * NEG_SLOPE;
        a1 = (a1 > 0.f) ? a1 : a1 * NEG_SLOPE;
        float w0 = __expf(a0), w1 = __expf(a1);
        denom += w0 + w1;
        uint4 d0 = *(const uint4*)&hs[(size_t)s0 * 256 + lane * 8];
        uint4 d1 = *(const uint4*)&hs[(size_t)s1 * 256 + lane * 8];
        acc_half8(acc, w0, d0);
        acc_half8(acc, w1, d1);
    }
    if (e < end) {
        int s = csrc[e];
        float a = es[s * 4 + h] + edh;
        a = (a > 0.f) ? a : a * NEG_SLOPE;
        float w = __expf(a);
        denom += w;
        uint4 d = *(const uint4*)&hs[(size_t)s * 256 + lane * 8];
        acc_half8(acc, w, d);
    }
    float inv = 1.f / (denom + EPS_F);
    const float4* bp = (const float4*)&bias[lane * 8];
    float4 b0 = bp[0], b1 = bp[1];
    float o[8];
    o[0] = fmaxf(acc[0] * inv + b0.x, 0.f);
    o[1] = fmaxf(acc[1] * inv + b0.y, 0.f);
    o[2] = fmaxf(acc[2] * inv + b0.z, 0.f);
    o[3] = fmaxf(acc[3] * inv + b0.w, 0.f);
    o[4] = fmaxf(acc[4] * inv + b1.x, 0.f);
    o[5] = fmaxf(acc[5] * inv + b1.y, 0.f);
    o[6] = fmaxf(acc[6] * inv + b1.z, 0.f);
    o[7] = fmaxf(acc[7] * inv + b1.w, 0.f);

    if (OUT) {
        uint32_t hw[4];
        #pragma unroll
        for (int q = 0; q < 4; q++) {
            __half2 hp = __floats2half2_rn(o[q * 2], o[q * 2 + 1]);
            hw[q] = *(uint32_t*)&hp;
        }
        *(uint4*)&outh[(size_t)warp * 256 + lane * 8] =
            make_uint4(hw[0], hw[1], hw[2], hw[3]);
    }

    if (AUX) {
        const float4* sT4 = (const float4*)saux;
        float ph[4];
        #pragma unroll
        for (int hh = 0; hh < 4; hh++) {
            float4 c0 = sT4[hh * 64 + lane * 2], c1 = sT4[hh * 64 + lane * 2 + 1];
            float p = o[0] * c0.x + o[1] * c0.y + o[2] * c0.z + o[3] * c0.w
                    + o[4] * c1.x + o[5] * c1.y + o[6] * c1.z + o[7] * c1.w;
            p += __shfl_xor_sync(0xffffffff, p, 16);
            p += __shfl_xor_sync(0xffffffff, p, 8);
            p += __shfl_xor_sync(0xffffffff, p, 4);
            p += __shfl_xor_sync(0xffffffff, p, 2);
            p += __shfl_xor_sync(0xffffffff, p, 1);
            ph[hh] = p;
        }
        if (lane == 0)
            ((float4*)auxout)[warp] = make_float4(ph[0], ph[1], ph[2], ph[3]);
    }
}

// ---------------------------------------------------------------------------
// prep_smat_all / wconv_all / splitsmall
// ---------------------------------------------------------------------------
__global__ void prep_smat_all(const float* __restrict__ Ws,
                              const float* __restrict__ Wd,
                              const float* __restrict__ as_,
                              const float* __restrict__ ad_,
                              float* __restrict__ cmbT_u,
                              float* __restrict__ cmbT_v,
                              float* __restrict__ wsatt2T,
                              float* __restrict__ vd2T) {
    int k = threadIdx.x, b = blockIdx.x;
    auto dot = [&](const float* W, const float* a, int h) {
        float s = 0.f;
        #pragma unroll 8
        for (int c = 0; c < 64; c++)
            s = fmaf(W[(size_t)k * 256 + h * 64 + c], a[h * 64 + c], s);
        return s;
    };
    if (b == 0) {
        for (int h = 0; h < 4; h++) cmbT_u[h * 256 + k] = dot(Ws, as_, h);
        for (int h = 0; h < 4; h++)
            cmbT_u[(4 + h) * 256 + k] = dot(Wd + 65536, ad_ + 256, h);
    } else if (b == 1) {
        for (int h = 0; h < 4; h++)
            cmbT_v[h * 256 + k] = dot(Ws + 65536, as_ + 256, h);
        for (int h = 0; h < 4; h++) cmbT_v[(4 + h) * 256 + k] = dot(Wd, ad_, h);
    } else if (b == 2) {
        for (int h = 0; h < 4; h++)
            wsatt2T[h * 256 + k] = dot(Ws + 3 * 65536, as_ + 3 * 256, h);
    } else {
        for (int h = 0; h < 4; h++)
            vd2T[h * 256 + k] = dot(Wd + 3 * 65536, ad_ + 3 * 256, h);
    }
}

// wconv: slices 0,1 -> bf16 hi/lo; slice 3 -> fp16 single; lin_w -> fp16 single
__global__ void wconv_all(const float* __restrict__ W_src,
                          const float* __restrict__ lin_w,
                          bf16* __restrict__ wt_hi, bf16* __restrict__ wt_lo,
                          __half* __restrict__ wt2h, __half* __restrict__ lth) {
    int b = blockIdx.x, k = threadIdx.x;
    if (b < 512) {
        int sl = b >> 8, n = b & 255;
        const float* W = W_src + (size_t)sl * 65536;
        float f = W[(size_t)k * 256 + n];
        bf16 h = __float2bfloat16(f);
        wt_hi[((size_t)sl * 256 + n) * 256 + k] = h;
        wt_lo[((size_t)sl * 256 + n) * 256 + k] =
            __float2bfloat16(f - __bfloat162float(h));
    } else if (b < 768) {
        int n = b - 512;
        float f = W_src[(size_t)3 * 65536 + (size_t)k * 256 + n];
        wt2h[(size_t)n * 256 + k] = __float2half_rn(f);
    } else {
        int n = b - 768;
        float f = lin_w[(size_t)k * 128 + n];
        lth[(size_t)n * 256 + k] = __float2half_rn(f);
    }
}

__global__ __launch_bounds__(256)
void splitsmall_kernel(const float* __restrict__ x, const float* __restrict__ cmbT,
                       bf16* __restrict__ hi, bf16* __restrict__ lo,
                       float* __restrict__ es, float* __restrict__ ed, int N) {
    __shared__ float sT[2048];
    for (int i = threadIdx.x; i < 2048; i += 256) sT[i] = cmbT[i];
    __syncthreads();
    int warp = (blockIdx.x * 256 + threadIdx.x) >> 5;
    int lane = threadIdx.x & 31;
    if (warp >= N) return;
    const float4* row = (const float4*)&x[(size_t)warp * 256 + lane * 8];
    float4 a0 = row[0], a1 = row[1];
    float v[8] = {a0.x, a0.y, a0.z, a0.w, a1.x, a1.y, a1.z, a1.w};

    uint32_t hw[4], lw[4];
    #pragma unroll
    for (int q = 0; q < 4; q++) {
        bf16 ha = __float2bfloat16(v[q * 2]), hb = __float2bfloat16(v[q * 2 + 1]);
        __nv_bfloat162 hp(ha, hb);
        __nv_bfloat162 lp(__float2bfloat16(v[q * 2] - __bfloat162float(ha)),
                          __float2bfloat16(v[q * 2 + 1] - __bfloat162float(hb)));
        hw[q] = *(uint32_t*)&hp;
        lw[q] = *(uint32_t*)&lp;
    }
    *(uint4*)&hi[(size_t)warp * 256 + lane * 8] = make_uint4(hw[0], hw[1], hw[2], hw[3]);
    *(uint4*)&lo[(size_t)warp * 256 + lane * 8] = make_uint4(lw[0], lw[1], lw[2], lw[3]);

    const float4* sT4 = (const float4*)sT;
    float p[8];
    #pragma unroll
    for (int h = 0; h < 8; h++) {
        float4 c0 = sT4[h * 64 + lane * 2], c1 = sT4[h * 64 + lane * 2 + 1];
        p[h] = a0.x * c0.x + a0.y * c0.y + a0.z * c0.z + a0.w * c0.w
             + a1.x * c1.x + a1.y * c1.y + a1.z * c1.z + a1.w * c1.w;
    }
    #pragma unroll
    for (int h = 0; h < 8; h++) {
        p[h] += __shfl_xor_sync(0xffffffff, p[h], 16);
        p[h] += __shfl_xor_sync(0xffffffff, p[h], 8);
        p[h] += __shfl_xor_sync(0xffffffff, p[h], 4);
        p[h] += __shfl_xor_sync(0xffffffff, p[h], 2);
        p[h] += __shfl_xor_sync(0xffffffff, p[h], 1);
    }
    if (lane == 0) {
        ((float4*)es)[warp] = make_float4(p[0], p[1], p[2], p[3]);
        ((float4*)ed)[warp] = make_float4(p[4], p[5], p[6], p[7]);
    }
}

// ---------------------------------------------------------------------------
// CSR build — both relations concatenated (proven kernels)
// ---------------------------------------------------------------------------
__global__ void zero_kernel(int* p, int n) {
    int i = blockIdx.x * blockDim.x + threadIdx.x;
    if (i < n) p[i] = 0;
}

__global__ void count2_kernel(const int* __restrict__ euv,
                              const int* __restrict__ evu,
                              int* __restrict__ cnt) {
    int e = blockIdx.x * blockDim.x + threadIdx.x;
    if (e < NE) atomicAdd(&cnt[euv[NE + e]], 1);
    else if (e < 2 * NE) atomicAdd(&cnt[50000 + evu[NE + (e - NE)]], 1);
}

__global__ __launch_bounds__(1024)
void scan1_kernel(const int* __restrict__ in, int* __restrict__ out,
                  int* __restrict__ bsums, int n) {
    __shared__ int sh[1024];
    int i = blockIdx.x * 1024 + threadIdx.x;
    int v = (i < n) ? in[i] : 0;
    sh[threadIdx.x] = v;
    __syncthreads();
    for (int off = 1; off < 1024; off <<= 1) {
        int t = (threadIdx.x >= off) ? sh[threadIdx.x - off] : 0;
        __syncthreads();
        sh[threadIdx.x] += t;
        __syncthreads();
    }
    if (i < n) out[i] = sh[threadIdx.x] - v;
    if (threadIdx.x == 1023) bsums[blockIdx.x] = sh[1023];
}

__global__ void scan2p_kernel(int* bsums, int nb) {
    __shared__ int sh[128];
    int t = threadIdx.x;
    int v = (t < nb) ? bsums[t] : 0;
    sh[t] = v;
    __syncthreads();
    for (int off = 1; off < 128; off <<= 1) {
        int x = (t >= off) ? sh[t - off] : 0;
        __syncthreads();
        sh[t] += x;
        __syncthreads();
    }
    if (t < nb) bsums[t] = sh[t] - v;   // exclusive
}

__global__ void scan3_kernel(int* out, const int* __restrict__ bsums, int n,
                             int total) {
    int i = blockIdx.x * blockDim.x + threadIdx.x;
    if (i < n) out[i] += bsums[i >> 10];
    if (i == 0) out[n] = total;
}

__global__ void fill2_kernel(const int* __restrict__ euv,
                             const int* __restrict__ evu,
                             const int* __restrict__ rowptr,
                             int* __restrict__ cursor, int* __restrict__ csrc) {
    int e = blockIdx.x * blockDim.x + threadIdx.x;
    if (e >= 2 * NE) return;
    int s, d;
    if (e < NE) { s = euv[e]; d = euv[NE + e]; }
    else { int e2 = e - NE; s = evu[e2]; d = 50000 + evu[NE + e2]; }
    int pos = atomicAdd(&cursor[d], 1);
    csrc[rowptr[d] + pos] = s;
}

// ---------------------------------------------------------------------------
// Host — single stream, plain launches only
// ---------------------------------------------------------------------------
static inline void* sym(const void* s) {
    void* p = nullptr;
    cudaGetSymbolAddress(&p, s);
    return p;
}

extern "C" void kernel_launch(void* const* d_in, const int* in_sizes, int n_in,
                              void* d_out, int out_size) {
    const float* x_u   = (const float*)d_in[0];
    const float* x_v   = (const float*)d_in[1];
    const float* W_src = (const float*)d_in[2];
    const float* W_dst = (const float*)d_in[3];
    const float* att_s = (const float*)d_in[4];
    const float* att_d = (const float*)d_in[5];
    const float* bias  = (const float*)d_in[6];
    const float* lin_w = (const float*)d_in[7];
    const float* lin_b = (const float*)d_in[8];
    const int* ei_uv   = (const int*)d_in[9];
    const int* ei_vu   = (const int*)d_in[10];
    float* out = (float*)d_out;

    __half *hs0 = (__half*)sym(g_hs0), *hs1 = (__half*)sym(g_hs1);
    bf16 *xu_hi = (bf16*)sym(g_xu_hi), *xu_lo = (bf16*)sym(g_xu_lo);
    bf16 *xv_hi = (bf16*)sym(g_xv_hi), *xv_lo = (bf16*)sym(g_xv_lo);
    __half *nv0h = (__half*)sym(g_nv0h), *nu1h = (__half*)sym(g_nu1h);
    float *es0 = (float*)sym(g_es0), *es1 = (float*)sym(g_es1), *es2 = (float*)sym(g_es2);
    float *ed0 = (float*)sym(g_ed0), *ed1 = (float*)sym(g_ed1), *ed2 = (float*)sym(g_ed2);
    float *cmbT_u = (float*)sym(g_cmbT_u), *cmbT_v = (float*)sym(g_cmbT_v);
    float *wsatt2T = (float*)sym(g_wsatt2T), *vd2T = (float*)sym(g_vd2T);
    bf16 *wt_hi = (bf16*)sym(g_wt_hi), *wt_lo = (bf16*)sym(g_wt_lo);
    __half *wt2h = (__half*)sym(g_wt2h), *lth = (__half*)sym(g_lth);
    int *rowptr = (int*)sym(g_rowptr), *csrc = (int*)sym(g_csrc);
    int *cnt = (int*)sym(g_cnt), *bsums = (int*)sym(g_bsums);

    cudaFuncSetAttribute(gemm_kernel<256, false, true>,
                         cudaFuncAttributeMaxDynamicSharedMemorySize, GSMEM);
    cudaFuncSetAttribute(gemm16_kernel<256, false, true>,
                         cudaFuncAttributeMaxDynamicSharedMemorySize, GSMEM16);
    cudaFuncSetAttribute(gemm16_kernel<128, true, false>,
                         cudaFuncAttributeMaxDynamicSharedMemorySize, GSMEM16);

    const size_t WSZ = 256 * 256, BSZ = 256;
    const int NB = (NALL + 1023) / 1024;   // 98

    // L0: tiny attention matrices
    prep_smat_all<<<4, 256>>>(W_src, W_dst, att_s, att_d,
                              cmbT_u, cmbT_v, wsatt2T, vd2T);
    // L1: weight convert (slices 0,1 bf16 split; slice 3 + lin fp16)
    wconv_all<<<896, 256>>>(W_src, lin_w, wt_hi, wt_lo, wt2h, lth);
    // L2: split + es0/ed1 for x_u
    splitsmall_kernel<<<6250, 256>>>(x_u, cmbT_u, xu_hi, xu_lo, es0, ed1, NU);
    // L3: gemm0 -> hs0 (fp16)   (ncu capture index)
    gemm_kernel<256, false, true><<<782, 256, GSMEM>>>(
        xu_hi, xu_lo, wt_hi + 0 * WSZ, wt_lo + 0 * WSZ, nullptr, hs0, NU);
    // L4: split + es1/ed0 for x_v
    splitsmall_kernel<<<6250, 256>>>(x_v, cmbT_v, xv_hi, xv_lo, es1, ed0, NV);
    // L5-L11: CSR (both relations concatenated)
    zero_kernel<<<(NALL + 255) / 256, 256>>>(cnt, NALL);
    count2_kernel<<<(2 * NE + 255) / 256, 256>>>(ei_uv, ei_vu, cnt);
    scan1_kernel<<<NB, 1024>>>(cnt, rowptr, bsums, NALL);
    scan2p_kernel<<<1, 128>>>(bsums, NB);
    scan3_kernel<<<(NALL + 255) / 256, 256>>>(rowptr, bsums, NALL, 2 * NE);
    zero_kernel<<<(NALL + 255) / 256, 256>>>(cnt, NALL);
    fill2_kernel<<<(2 * NE + 255) / 256, 256>>>(ei_uv, ei_vu, rowptr, cnt, csrc);

    // L12: agg0 (hs0 -> nv0h fp16, +es2)
    agg_kernel<1, 1><<<6250, 256>>>(hs0, es0, ed0, rowptr, csrc, bias + 0 * BSZ,
                                    nv0h, wsatt2T, es2, NV);
    // L13: gemm1 (xv -> hs1, fp16 out)
    gemm_kernel<256, false, true><<<782, 256, GSMEM>>>(
        xv_hi, xv_lo, wt_hi + 1 * WSZ, wt_lo + 1 * WSZ, nullptr, hs1, NV);
    // L14: agg1 (hs1 -> ed2 only; nu0 output is dead)
    agg_kernel<1, 0><<<6250, 256>>>(hs1, es1, ed1, rowptr + 50000, csrc,
                                    bias + 1 * BSZ, nullptr, vd2T, ed2, NU);
    // L15: gemm2 (nv0h -> hs0, single fp16)
    gemm16_kernel<256, false, true><<<782, 256, GSMEM16>>>(
        nv0h, wt2h, nullptr, hs0, NV);
    // L16: agg2 (hs0 -> nu1h fp16)
    agg_kernel<0, 1><<<6250, 256>>>(hs0, es2, ed2, rowptr + 50000, csrc,
                                    bias + 3 * BSZ, nu1h, nullptr, nullptr, NU);
    // L17: final linear (single fp16, fp32 out)
    gemm16_kernel<128, true, false><<<391, 256, GSMEM16>>>(
        nu1h, lth, lin_b, out, NU);
}

// round 15
// speedup vs baseline: 1.7810x; 1.1952x over previous
#include <cuda_runtime.h>
#include <cuda_bf16.h>
#include <cuda_fp16.h>
#include <cstdint>

static const int NU = 50000;
static const int NV = 50000;
static const int NE = 500000;
static const int NALL = 100000;          // concatenated dst-node space
#define NEG_SLOPE 0.2f
#define EPS_F 1e-16f
#define GSMEM16 40960

// ---------------------------------------------------------------------------
// Static device scratch
// ---------------------------------------------------------------------------
__device__ __align__(128) __half g_hs0[50048 * 256];
__device__ __align__(128) __half g_hs1[50048 * 256];
__device__ __align__(128) __half g_xuh[50048 * 256];
__device__ __align__(128) __half g_xvh[50048 * 256];
__device__ __align__(128) __half g_nv0h[50048 * 256];
__device__ __align__(128) __half g_nu1h[50048 * 256];
__device__ __align__(128) float g_es0[50048 * 4], g_es1[50048 * 4], g_es2[50048 * 4];
__device__ __align__(128) float g_ed0[50048 * 4], g_ed1[50048 * 4], g_ed2[50048 * 4];
__device__ __align__(128) float g_cmbT_u[8 * 256], g_cmbT_v[8 * 256];
__device__ __align__(128) float g_wsatt2T[4 * 256], g_vd2T[4 * 256];
__device__ __align__(128) __half g_wth[3 * 256 * 256];
__device__ __align__(128) __half g_lth[128 * 256];
__device__ __align__(128) int g_rowptr[100001];
__device__ __align__(128) int g_csrc[1000000];
__device__ __align__(128) int g_cnt[100001], g_bsums[128];

// ---------------------------------------------------------------------------
// helpers
// ---------------------------------------------------------------------------
__device__ __forceinline__ uint32_t smem_u32(const void* p) {
    uint32_t a;
    asm("{ .reg .u64 t; cvta.to.shared.u64 t, %1; cvt.u32.u64 %0, t; }"
        : "=r"(a) : "l"(p));
    return a;
}

__device__ __forceinline__ void cp16(uint32_t dst, const void* src) {
    asm volatile("cp.async.cg.shared.global [%0], [%1], 16;"
                 :: "r"(dst), "l"(src));
}

__device__ __forceinline__ void ldsm4(uint32_t& r0, uint32_t& r1, uint32_t& r2,
                                      uint32_t& r3, uint32_t addr) {
    asm volatile("ldmatrix.sync.aligned.m8n8.x4.shared.b16 {%0,%1,%2,%3}, [%4];"
                 : "=r"(r0), "=r"(r1), "=r"(r2), "=r"(r3) : "r"(addr));
}

__device__ __forceinline__ void mma_fp16(float* c, const uint32_t* a,
                                         const uint32_t* b) {
    asm volatile(
        "mma.sync.aligned.m16n8k16.row.col.f32.f16.f16.f32 "
        "{%0,%1,%2,%3}, {%4,%5,%6,%7}, {%8,%9}, {%0,%1,%2,%3};"
        : "+f"(c[0]), "+f"(c[1]), "+f"(c[2]), "+f"(c[3])
        : "r"(a[0]), "r"(a[1]), "r"(a[2]), "r"(a[3]), "r"(b[0]), "r"(b[1]));
}

// ---------------------------------------------------------------------------
// GEMM16 (single-term fp16): C = A@B^T, A/B fp16.  (R14-proven kernel)
// ---------------------------------------------------------------------------
template<int NSTR, bool BIAS, bool HOUT>
__global__ __launch_bounds__(256)
void gemm16_kernel(const __half* __restrict__ A, const __half* __restrict__ B,
                   const float* __restrict__ bias, void* __restrict__ Cv, int M) {
    extern __shared__ __align__(128) char smg[];
    const uint32_t sb = smem_u32(smg);
    const int tid = threadIdx.x, lane = tid & 31, wid = tid >> 5;
    const int wm = wid >> 2, wn = wid & 3;
    const int mt = (M + 127) / 128;
    const int bm = (blockIdx.x % mt) * 128, bn = (blockIdx.x / mt) * 128;

    const char* src[2] = {(const char*)(A + (size_t)bm * 256),
                          (const char*)(B + (size_t)bn * 256)};

    uint32_t aB[4], bB[2];
    {
        int ar = wm * 64 + (lane & 15), ac = (lane >> 4) * 8;
        #pragma unroll
        for (int i = 0; i < 4; i++)
            aB[i] = sb + (uint32_t)(ar + i * 16) * 80 + ac * 2;
        int br = wn * 32 + ((lane >> 4) << 3) + (lane & 7);
        int bc = ((lane >> 3) & 1) * 8;
        #pragma unroll
        for (int p = 0; p < 2; p++)
            bB[p] = sb + 10240 + (uint32_t)(br + p * 16) * 80 + bc * 2;
    }

    float acc[4][4][4];
    #pragma unroll
    for (int i = 0; i < 4; i++)
        #pragma unroll
        for (int j = 0; j < 4; j++)
            #pragma unroll
            for (int q = 0; q < 4; q++) acc[i][j][q] = 0.f;

    auto load_stage = [&](int kc, int buf) {
        #pragma unroll
        for (int arr = 0; arr < 2; arr++) {
            const char* s = src[arr] + kc * 64;
            uint32_t d = sb + buf * 20480 + arr * 10240;
            #pragma unroll
            for (int t2 = 0; t2 < 2; t2++) {
                int cid = t2 * 256 + tid, row = cid >> 2, c = cid & 3;
                cp16(d + row * 80 + c * 16, s + (size_t)row * 512 + c * 16);
            }
        }
        asm volatile("cp.async.commit_group;");
    };

    load_stage(0, 0);
    for (int kc = 0; kc < 8; kc++) {
        int buf = kc & 1;
        asm volatile("cp.async.wait_group 0;");
        __syncthreads();
        if (kc < 7) load_stage(kc + 1, buf ^ 1);
        uint32_t bo = (uint32_t)buf * 20480;
        #pragma unroll
        for (int ks = 0; ks < 2; ks++) {
            uint32_t ah[4][4], bh[4][2];
            #pragma unroll
            for (int i = 0; i < 4; i++)
                ldsm4(ah[i][0], ah[i][1], ah[i][2], ah[i][3], aB[i] + bo + ks * 32);
            #pragma unroll
            for (int p = 0; p < 2; p++) {
                uint32_t r0, r1, r2, r3;
                ldsm4(r0, r1, r2, r3, bB[p] + bo + ks * 32);
                bh[p * 2][0] = r0; bh[p * 2][1] = r1;
                bh[p * 2 + 1][0] = r2; bh[p * 2 + 1][1] = r3;
            }
            #pragma unroll
            for (int i = 0; i < 4; i++)
                #pragma unroll
                for (int j = 0; j < 4; j++)
                    mma_fp16(acc[i][j], ah[i], bh[j]);
        }
    }

    #pragma unroll
    for (int i = 0; i < 4; i++) {
        int r0 = bm + wm * 64 + i * 16 + (lane >> 2);
        #pragma unroll
        for (int j = 0; j < 4; j++) {
            int cc = bn + wn * 32 + j * 8 + 2 * (lane & 3);
            float b0 = 0.f, b1 = 0.f;
            if (BIAS) { b0 = __ldg(&bias[cc]); b1 = __ldg(&bias[cc + 1]); }
            if (HOUT) {
                __half* C = (__half*)Cv;
                if (r0 < M)
                    *(__half2*)&C[(size_t)r0 * NSTR + cc] =
                        __floats2half2_rn(acc[i][j][0] + b0, acc[i][j][1] + b1);
                if (r0 + 8 < M)
                    *(__half2*)&C[(size_t)(r0 + 8) * NSTR + cc] =
                        __floats2half2_rn(acc[i][j][2] + b0, acc[i][j][3] + b1);
            } else {
                float* C = (float*)Cv;
                if (r0 < M)
                    *(float2*)&C[(size_t)r0 * NSTR + cc] =
                        make_float2(acc[i][j][0] + b0, acc[i][j][1] + b1);
                if (r0 + 8 < M)
                    *(float2*)&C[(size_t)(r0 + 8) * NSTR + cc] =
                        make_float2(acc[i][j][2] + b0, acc[i][j][3] + b1);
            }
        }
    }
}

// ---------------------------------------------------------------------------
// Aggregation: softmax + gather(fp16 hs) + bias + relu.  (R14-proven)
// OUT: 1 = store fp16 row, 0 = no output store.  AUX: aux dot from registers.
// ---------------------------------------------------------------------------
__device__ __forceinline__ void acc_half8(float* acc, float w, uint4 d) {
    __half2* hh = (__half2*)&d;
    #pragma unroll
    for (int q = 0; q < 4; q++) {
        float2 f = __half22float2(hh[q]);
        acc[q * 2]     = fmaf(w, f.x, acc[q * 2]);
        acc[q * 2 + 1] = fmaf(w, f.y, acc[q * 2 + 1]);
    }
}

template<int AUX, int OUT>
__global__ __launch_bounds__(256)
void agg_kernel(const __half* __restrict__ hs, const float* __restrict__ es,
                const float* __restrict__ ed, const int* __restrict__ rowptr,
                const int* __restrict__ csrc, const float* __restrict__ bias,
                __half* __restrict__ outh,
                const float* __restrict__ auxT, float* __restrict__ auxout,
                int Nd) {
    __shared__ float saux[1024];
    if (AUX) {
        for (int i = threadIdx.x; i < 1024; i += 256) saux[i] = auxT[i];
        __syncthreads();
    }
    int warp = blockIdx.x * 8 + (threadIdx.x >> 5);
    int lane = threadIdx.x & 31;
    if (warp >= Nd) return;
    int h = lane >> 3;
    float edh = ed[warp * 4 + h];
    int beg = rowptr[warp], end = rowptr[warp + 1];
    float denom = 0.f;
    float acc[8] = {0.f, 0.f, 0.f, 0.f, 0.f, 0.f, 0.f, 0.f};
    int e = beg;
    for (; e + 2 <= end; e += 2) {
        int s0 = csrc[e], s1 = csrc[e + 1];
        float a0 = es[s0 * 4 + h] + edh;
        float a1 = es[s1 * 4 + h] + edh;
        a0 = (a0 > 0.f) ? a0 : a0 * NEG_SLOPE;
        a1 = (a1 > 0.f) ? a1 : a1 * NEG_SLOPE;
        float w0 = __expf(a0), w1 = __expf(a1);
        denom += w0 + w1;
        uint4 d0 = *(const uint4*)&hs[(size_t)s0 * 256 + lane * 8];
        uint4 d1 = *(const uint4*)&hs[(size_t)s1 * 256 + lane * 8];
        acc_half8(acc, w0, d0);
        acc_half8(acc, w1, d1);
    }
    if (e < end) {
        int s = csrc[e];
        float a = es[s * 4 + h] + edh;
        a = (a > 0.f) ? a : a * NEG_SLOPE;
        float w = __expf(a);
        denom += w;
        uint4 d = *(const uint4*)&hs[(size_t)s * 256 + lane * 8];
        acc_half8(acc, w, d);
    }
    float inv = 1.f / (denom + EPS_F);
    const float4* bp = (const float4*)&bias[lane * 8];
    float4 b0 = bp[0], b1 = bp[1];
    float o[8];
    o[0] = fmaxf(acc[0] * inv + b0.x, 0.f);
    o[1] = fmaxf(acc[1] * inv + b0.y, 0.f);
    o[2] = fmaxf(acc[2] * inv + b0.z, 0.f);
    o[3] = fmaxf(acc[3] * inv + b0.w, 0.f);
    o[4] = fmaxf(acc[4] * inv + b1.x, 0.f);
    o[5] = fmaxf(acc[5] * inv + b1.y, 0.f);
    o[6] = fmaxf(acc[6] * inv + b1.z, 0.f);
    o[7] = fmaxf(acc[7] * inv + b1.w, 0.f);

    if (OUT) {
        uint32_t hw[4];
        #pragma unroll
        for (int q = 0; q < 4; q++) {
            __half2 hp = __floats2half2_rn(o[q * 2], o[q * 2 + 1]);
            hw[q] = *(uint32_t*)&hp;
        }
        *(uint4*)&outh[(size_t)warp * 256 + lane * 8] =
            make_uint4(hw[0], hw[1], hw[2], hw[3]);
    }

    if (AUX) {
        const float4* sT4 = (const float4*)saux;
        float ph[4];
        #pragma unroll
        for (int hh = 0; hh < 4; hh++) {
            float4 c0 = sT4[hh * 64 + lane * 2], c1 = sT4[hh * 64 + lane * 2 + 1];
            float p = o[0] * c0.x + o[1] * c0.y + o[2] * c0.z + o[3] * c0.w
                    + o[4] * c1.x + o[5] * c1.y + o[6] * c1.z + o[7] * c1.w;
            p += __shfl_xor_sync(0xffffffff, p, 16);
            p += __shfl_xor_sync(0xffffffff, p, 8);
            p += __shfl_xor_sync(0xffffffff, p, 4);
            p += __shfl_xor_sync(0xffffffff, p, 2);
            p += __shfl_xor_sync(0xffffffff, p, 1);
            ph[hh] = p;
        }
        if (lane == 0)
            ((float4*)auxout)[warp] = make_float4(ph[0], ph[1], ph[2], ph[3]);
    }
}

// ---------------------------------------------------------------------------
// prep_smat_all / wconv_all / split_h
// ---------------------------------------------------------------------------
__global__ void prep_smat_all(const float* __restrict__ Ws,
                              const float* __restrict__ Wd,
                              const float* __restrict__ as_,
                              const float* __restrict__ ad_,
                              float* __restrict__ cmbT_u,
                              float* __restrict__ cmbT_v,
                              float* __restrict__ wsatt2T,
                              float* __restrict__ vd2T) {
    int k = threadIdx.x, b = blockIdx.x;
    auto dot = [&](const float* W, const float* a, int h) {
        float s = 0.f;
        #pragma unroll 8
        for (int c = 0; c < 64; c++)
            s = fmaf(W[(size_t)k * 256 + h * 64 + c], a[h * 64 + c], s);
        return s;
    };
    if (b == 0) {
        for (int h = 0; h < 4; h++) cmbT_u[h * 256 + k] = dot(Ws, as_, h);
        for (int h = 0; h < 4; h++)
            cmbT_u[(4 + h) * 256 + k] = dot(Wd + 65536, ad_ + 256, h);
    } else if (b == 1) {
        for (int h = 0; h < 4; h++)
            cmbT_v[h * 256 + k] = dot(Ws + 65536, as_ + 256, h);
        for (int h = 0; h < 4; h++) cmbT_v[(4 + h) * 256 + k] = dot(Wd, ad_, h);
    } else if (b == 2) {
        for (int h = 0; h < 4; h++)
            wsatt2T[h * 256 + k] = dot(Ws + 3 * 65536, as_ + 3 * 256, h);
    } else {
        for (int h = 0; h < 4; h++)
            vd2T[h * 256 + k] = dot(Wd + 3 * 65536, ad_ + 3 * 256, h);
    }
}

// wconv: W_src slices 0,1,3 -> fp16 [n][k]; lin_w -> fp16 [n][k]
__global__ void wconv_all(const float* __restrict__ W_src,
                          const float* __restrict__ lin_w,
                          __half* __restrict__ wth, __half* __restrict__ lth) {
    int b = blockIdx.x, k = threadIdx.x;
    if (b < 768) {
        int sl = b >> 8, n = b & 255;
        const float* W = W_src + (size_t)(sl == 2 ? 3 : sl) * 65536;
        wth[((size_t)sl * 256 + n) * 256 + k] =
            __float2half_rn(W[(size_t)k * 256 + n]);
    } else {
        int n = b - 768;
        lth[(size_t)n * 256 + k] = __float2half_rn(lin_w[(size_t)k * 128 + n]);
    }
}

// split_h: x fp32 -> fp16, plus es/ed dots (fp32 inputs, exact as before)
__global__ __launch_bounds__(256)
void split_h_kernel(const float* __restrict__ x, const float* __restrict__ cmbT,
                    __half* __restrict__ xh,
                    float* __restrict__ es, float* __restrict__ ed, int N) {
    __shared__ float sT[2048];
    for (int i = threadIdx.x; i < 2048; i += 256) sT[i] = cmbT[i];
    __syncthreads();
    int warp = (blockIdx.x * 256 + threadIdx.x) >> 5;
    int lane = threadIdx.x & 31;
    if (warp >= N) return;
    const float4* row = (const float4*)&x[(size_t)warp * 256 + lane * 8];
    float4 a0 = row[0], a1 = row[1];

    uint32_t hw[4];
    {
        __half2 p0 = __floats2half2_rn(a0.x, a0.y);
        __half2 p1 = __floats2half2_rn(a0.z, a0.w);
        __half2 p2 = __floats2half2_rn(a1.x, a1.y);
        __half2 p3 = __floats2half2_rn(a1.z, a1.w);
        hw[0] = *(uint32_t*)&p0; hw[1] = *(uint32_t*)&p1;
        hw[2] = *(uint32_t*)&p2; hw[3] = *(uint32_t*)&p3;
    }
    *(uint4*)&xh[(size_t)warp * 256 + lane * 8] =
        make_uint4(hw[0], hw[1], hw[2], hw[3]);

    const float4* sT4 = (const float4*)sT;
    float p[8];
    #pragma unroll
    for (int h = 0; h < 8; h++) {
        float4 c0 = sT4[h * 64 + lane * 2], c1 = sT4[h * 64 + lane * 2 + 1];
        p[h] = a0.x * c0.x + a0.y * c0.y + a0.z * c0.z + a0.w * c0.w
             + a1.x * c1.x + a1.y * c1.y + a1.z * c1.z + a1.w * c1.w;
    }
    #pragma unroll
    for (int h = 0; h < 8; h++) {
        p[h] += __shfl_xor_sync(0xffffffff, p[h], 16);
        p[h] += __shfl_xor_sync(0xffffffff, p[h], 8);
        p[h] += __shfl_xor_sync(0xffffffff, p[h], 4);
        p[h] += __shfl_xor_sync(0xffffffff, p[h], 2);
        p[h] += __shfl_xor_sync(0xffffffff, p[h], 1);
    }
    if (lane == 0) {
        ((float4*)es)[warp] = make_float4(p[0], p[1], p[2], p[3]);
        ((float4*)ed)[warp] = make_float4(p[4], p[5], p[6], p[7]);
    }
}

// ---------------------------------------------------------------------------
// CSR build — both relations concatenated (proven kernels)
// ---------------------------------------------------------------------------
__global__ void zero_kernel(int* p, int n) {
    int i = blockIdx.x * blockDim.x + threadIdx.x;
    if (i < n) p[i] = 0;
}

__global__ void count2_kernel(const int* __restrict__ euv,
                              const int* __restrict__ evu,
                              int* __restrict__ cnt) {
    int e = blockIdx.x * blockDim.x + threadIdx.x;
    if (e < NE) atomicAdd(&cnt[euv[NE + e]], 1);
    else if (e < 2 * NE) atomicAdd(&cnt[50000 + evu[NE + (e - NE)]], 1);
}

__global__ __launch_bounds__(1024)
void scan1_kernel(const int* __restrict__ in, int* __restrict__ out,
                  int* __restrict__ bsums, int n) {
    __shared__ int sh[1024];
    int i = blockIdx.x * 1024 + threadIdx.x;
    int v = (i < n) ? in[i] : 0;
    sh[threadIdx.x] = v;
    __syncthreads();
    for (int off = 1; off < 1024; off <<= 1) {
        int t = (threadIdx.x >= off) ? sh[threadIdx.x - off] : 0;
        __syncthreads();
        sh[threadIdx.x] += t;
        __syncthreads();
    }
    if (i < n) out[i] = sh[threadIdx.x] - v;
    if (threadIdx.x == 1023) bsums[blockIdx.x] = sh[1023];
}

__global__ void scan2p_kernel(int* bsums, int nb) {
    __shared__ int sh[128];
    int t = threadIdx.x;
    int v = (t < nb) ? bsums[t] : 0;
    sh[t] = v;
    __syncthreads();
    for (int off = 1; off < 128; off <<= 1) {
        int x = (t >= off) ? sh[t - off] : 0;
        __syncthreads();
        sh[t] += x;
        __syncthreads();
    }
    if (t < nb) bsums[t] = sh[t] - v;   // exclusive
}

__global__ void scan3_kernel(int* out, const int* __restrict__ bsums, int n,
                             int total) {
    int i = blockIdx.x * blockDim.x + threadIdx.x;
    if (i < n) out[i] += bsums[i >> 10];
    if (i == 0) out[n] = total;
}

__global__ void fill2_kernel(const int* __restrict__ euv,
                             const int* __restrict__ evu,
                             const int* __restrict__ rowptr,
                             int* __restrict__ cursor, int* __restrict__ csrc) {
    int e = blockIdx.x * blockDim.x + threadIdx.x;
    if (e >= 2 * NE) return;
    int s, d;
    if (e < NE) { s = euv[e]; d = euv[NE + e]; }
    else { int e2 = e - NE; s = evu[e2]; d = 50000 + evu[NE + e2]; }
    int pos = atomicAdd(&cursor[d], 1);
    csrc[rowptr[d] + pos] = s;
}

// ---------------------------------------------------------------------------
// Host — single stream, plain launches only
// ---------------------------------------------------------------------------
static inline void* sym(const void* s) {
    void* p = nullptr;
    cudaGetSymbolAddress(&p, s);
    return p;
}

extern "C" void kernel_launch(void* const* d_in, const int* in_sizes, int n_in,
                              void* d_out, int out_size) {
    const float* x_u   = (const float*)d_in[0];
    const float* x_v   = (const float*)d_in[1];
    const float* W_src = (const float*)d_in[2];
    const float* W_dst = (const float*)d_in[3];
    const float* att_s = (const float*)d_in[4];
    const float* att_d = (const float*)d_in[5];
    const float* bias  = (const float*)d_in[6];
    const float* lin_w = (const float*)d_in[7];
    const float* lin_b = (const float*)d_in[8];
    const int* ei_uv   = (const int*)d_in[9];
    const int* ei_vu   = (const int*)d_in[10];
    float* out = (float*)d_out;

    __half *hs0 = (__half*)sym(g_hs0), *hs1 = (__half*)sym(g_hs1);
    __half *xuh = (__half*)sym(g_xuh), *xvh = (__half*)sym(g_xvh);
    __half *nv0h = (__half*)sym(g_nv0h), *nu1h = (__half*)sym(g_nu1h);
    float *es0 = (float*)sym(g_es0), *es1 = (float*)sym(g_es1), *es2 = (float*)sym(g_es2);
    float *ed0 = (float*)sym(g_ed0), *ed1 = (float*)sym(g_ed1), *ed2 = (float*)sym(g_ed2);
    float *cmbT_u = (float*)sym(g_cmbT_u), *cmbT_v = (float*)sym(g_cmbT_v);
    float *wsatt2T = (float*)sym(g_wsatt2T), *vd2T = (float*)sym(g_vd2T);
    __half *wth = (__half*)sym(g_wth), *lth = (__half*)sym(g_lth);
    int *rowptr = (int*)sym(g_rowptr), *csrc = (int*)sym(g_csrc);
    int *cnt = (int*)sym(g_cnt), *bsums = (int*)sym(g_bsums);

    cudaFuncSetAttribute(gemm16_kernel<256, false, true>,
                         cudaFuncAttributeMaxDynamicSharedMemorySize, GSMEM16);
    cudaFuncSetAttribute(gemm16_kernel<128, true, false>,
                         cudaFuncAttributeMaxDynamicSharedMemorySize, GSMEM16);

    const size_t WSZ = 256 * 256, BSZ = 256;
    const int NB = (NALL + 1023) / 1024;   // 98

    // L0: tiny attention matrices
    prep_smat_all<<<4, 256>>>(W_src, W_dst, att_s, att_d,
                              cmbT_u, cmbT_v, wsatt2T, vd2T);
    // L1: weight convert (all fp16)
    wconv_all<<<896, 256>>>(W_src, lin_w, wth, lth);
    // L2: x_u -> fp16 + es0/ed1
    split_h_kernel<<<6250, 256>>>(x_u, cmbT_u, xuh, es0, ed1, NU);
    // L3: gemm0 (xu -> hs0)   (ncu capture index)
    gemm16_kernel<256, false, true><<<782, 256, GSMEM16>>>(
        xuh, wth + 0 * WSZ, nullptr, hs0, NU);
    // L4: x_v -> fp16 + es1/ed0
    split_h_kernel<<<6250, 256>>>(x_v, cmbT_v, xvh, es1, ed0, NV);
    // L5-L11: CSR (both relations concatenated)
    zero_kernel<<<(NALL + 255) / 256, 256>>>(cnt, NALL);
    count2_kernel<<<(2 * NE + 255) / 256, 256>>>(ei_uv, ei_vu, cnt);
    scan1_kernel<<<NB, 1024>>>(cnt, rowptr, bsums, NALL);
    scan2p_kernel<<<1, 128>>>(bsums, NB);
    scan3_kernel<<<(NALL + 255) / 256, 256>>>(rowptr, bsums, NALL, 2 * NE);
    zero_kernel<<<(NALL + 255) / 256, 256>>>(cnt, NALL);
    fill2_kernel<<<(2 * NE + 255) / 256, 256>>>(ei_uv, ei_vu, rowptr, cnt, csrc);

    // L12: agg0 (hs0 -> nv0h fp16, +es2)
    agg_kernel<1, 1><<<6250, 256>>>(hs0, es0, ed0, rowptr, csrc, bias + 0 * BSZ,
                                    nv0h, wsatt2T, es2, NV);
    // L13: gemm1 (xv -> hs1)
    gemm16_kernel<256, false, true><<<782, 256, GSMEM16>>>(
        xvh, wth + 1 * WSZ, nullptr, hs1, NV);
    // L14: agg1 (hs1 -> ed2 only; nu0 output dead)
    agg_kernel<1, 0><<<6250, 256>>>(hs1, es1, ed1, rowptr + 50000, csrc,
                                    bias + 1 * BSZ, nullptr, vd2T, ed2, NU);
    // L15: gemm2 (nv0h -> hs0)
    gemm16_kernel<256, false, true><<<782, 256, GSMEM16>>>(
        nv0h, wth + 2 * WSZ, nullptr, hs0, NV);
    // L16: agg2 (hs0 -> nu1h fp16)
    agg_kernel<0, 1><<<6250, 256>>>(hs0, es2, ed2, rowptr + 50000, csrc,
                                    bias + 3 * BSZ, nu1h, nullptr, nullptr, NU);
    // L17: final linear (fp32 out)
    gemm16_kernel<128, true, false><<<391, 256, GSMEM16>>>(
        nu1h, lth, lin_b, out, NU);
}